// round 1
// baseline (speedup 1.0000x reference)
#include <cuda_runtime.h>

#define BB 4
#define SS 2048
#define DD 1024
#define HH 16
#define HDD 64
#define NTOK (BB*SS)

// Scratch (static __device__ arrays; no allocation allowed)
__device__ float g_q[BB*HH*SS*HDD];
__device__ float g_k[BB*HH*SS*HDD];
__device__ float g_v[BB*HH*SS*HDD];
__device__ float g_o[NTOK*DD];

// ---------------------------------------------------------------------------
// QKV projection: out[b,h,s,e] = (x[b,s,:] @ W[h][:,e] + bias[h,e]) * scale
// BM=128, BN=64 (one head), BK=16, 256 threads, 8x4 per-thread tile.
// ---------------------------------------------------------------------------
__global__ __launch_bounds__(256, 1) void qkv_kernel(
    const float* __restrict__ x,
    const float* __restrict__ Wq, const float* __restrict__ bq,
    const float* __restrict__ Wk, const float* __restrict__ bk,
    const float* __restrict__ Wv, const float* __restrict__ bv)
{
    const int mt    = blockIdx.x;   // 0..63 token tiles
    const int h     = blockIdx.y;   // 0..15
    const int which = blockIdx.z;   // 0:q 1:k 2:v

    const float* W; const float* bias; float* out; float scale;
    if (which == 0)      { W = Wq; bias = bq; out = g_q; scale = 0.125f; }
    else if (which == 1) { W = Wk; bias = bk; out = g_k; scale = 1.0f;  }
    else                 { W = Wv; bias = bv; out = g_v; scale = 1.0f;  }
    W    += (size_t)h * DD * HDD;
    bias += h * HDD;

    __shared__ float As[16][132];   // transposed x tile [k][row], padded
    __shared__ float Bs[16][64];    // W tile [k][col]

    const int t  = threadIdx.x;
    const int tx = t & 15;          // col group (4 cols)
    const int ty = t >> 4;          // row group (8 rows)
    const int m0 = mt * 128;
    const int lrow = t >> 2;        // 0..63 (A loader)
    const int lkg  = t & 3;         // 0..3  (A loader k-group)

    float acc[8][4];
#pragma unroll
    for (int i = 0; i < 8; ++i)
#pragma unroll
        for (int j = 0; j < 4; ++j) acc[i][j] = 0.0f;

    for (int k0 = 0; k0 < DD; k0 += 16) {
        float4 a0 = *(const float4*)&x[(size_t)(m0 + lrow)      * DD + k0 + lkg * 4];
        float4 a1 = *(const float4*)&x[(size_t)(m0 + lrow + 64) * DD + k0 + lkg * 4];
        float4 b0 = *(const float4*)&W[(size_t)(k0 + ty) * HDD + tx * 4];
        __syncthreads();
        As[lkg*4 + 0][lrow] = a0.x; As[lkg*4 + 1][lrow] = a0.y;
        As[lkg*4 + 2][lrow] = a0.z; As[lkg*4 + 3][lrow] = a0.w;
        As[lkg*4 + 0][lrow + 64] = a1.x; As[lkg*4 + 1][lrow + 64] = a1.y;
        As[lkg*4 + 2][lrow + 64] = a1.z; As[lkg*4 + 3][lrow + 64] = a1.w;
        *(float4*)&Bs[ty][tx * 4] = b0;
        __syncthreads();
#pragma unroll
        for (int kk = 0; kk < 16; ++kk) {
            float4 a04 = *(const float4*)&As[kk][ty * 8];
            float4 a14 = *(const float4*)&As[kk][ty * 8 + 4];
            float4 bv4 = *(const float4*)&Bs[kk][tx * 4];
            float av[8] = {a04.x, a04.y, a04.z, a04.w, a14.x, a14.y, a14.z, a14.w};
            float bv_[4] = {bv4.x, bv4.y, bv4.z, bv4.w};
#pragma unroll
            for (int i = 0; i < 8; ++i)
#pragma unroll
                for (int j = 0; j < 4; ++j)
                    acc[i][j] = fmaf(av[i], bv_[j], acc[i][j]);
        }
    }

    float bb[4];
#pragma unroll
    for (int j = 0; j < 4; ++j) bb[j] = bias[tx * 4 + j];
#pragma unroll
    for (int i = 0; i < 8; ++i) {
        int r    = m0 + ty * 8 + i;        // global token
        int bidx = r >> 11;                // / S
        int s    = r & (SS - 1);
        float4 v;
        v.x = (acc[i][0] + bb[0]) * scale;
        v.y = (acc[i][1] + bb[1]) * scale;
        v.z = (acc[i][2] + bb[2]) * scale;
        v.w = (acc[i][3] + bb[3]) * scale;
        *(float4*)&out[(((size_t)bidx * HH + h) * SS + s) * HDD + tx * 4] = v;
    }
}

// ---------------------------------------------------------------------------
// Flash attention (causal): one block per (qtile=128 rows, h, b).
// 8 warps; each warp owns 16 q-rows; lane = (rg, jg): 4 rows x 8 cols.
// Smem: Qs[row][e] (chunk-swizzled), Ks[j][e] (chunk-swizzled), Vs[j][e],
//       Ps[row][j] (stride 65).
// ---------------------------------------------------------------------------
#define ATTN_SMEM_FLOATS (128*64 + 64*64 + 64*64 + 128*65)

__global__ __launch_bounds__(256, 1) void attn_kernel()
{
    extern __shared__ float sm[];
    float* Qs = sm;             // 8192 floats
    float* Ks = sm + 8192;      // 4096
    float* Vs = sm + 12288;     // 4096
    float* Ps = sm + 16384;     // 8320

    const int qt = blockIdx.x;  // 0..15
    const int h  = blockIdx.y;  // 0..15
    const int b  = blockIdx.z;  // 0..3
    const int q0 = qt * 128;

    const int t    = threadIdx.x;
    const int w    = t >> 5;
    const int lane = t & 31;
    const int jg   = lane & 7;   // col group (8 cols)
    const int rg   = lane >> 3;  // row group (4 rows)
    const int rowbase = w * 16 + rg * 4;

    const size_t base = ((size_t)(b * HH + h)) * SS * HDD;
    const float* qp = g_q + base;
    const float* kp = g_k + base;
    const float* vp = g_v + base;

    // Load Q tile (swizzle chunk by (row>>2)&7)
    {
        int row = t >> 4, eg = t & 15;
#pragma unroll
        for (int it = 0; it < 8; ++it, row += 16) {
            float4 qv = *(const float4*)&qp[(size_t)(q0 + row) * HDD + eg * 4];
            *(float4*)&Qs[row * 64 + ((eg ^ ((row >> 2) & 7)) << 2)] = qv;
        }
    }

    float o[4][8];
    float mrow[4], lrow[4];
#pragma unroll
    for (int rr = 0; rr < 4; ++rr) {
        mrow[rr] = -1e30f; lrow[rr] = 0.0f;
#pragma unroll
        for (int ee = 0; ee < 8; ++ee) o[rr][ee] = 0.0f;
    }

    const int nkt = qt * 2 + 2;
    for (int kt = 0; kt < nkt; ++kt) {
        const int k0 = kt * 64;
        __syncthreads();
        {
            int row = t >> 4, eg = t & 15;
#pragma unroll
            for (int it = 0; it < 4; ++it, row += 16) {
                float4 kv = *(const float4*)&kp[(size_t)(k0 + row) * HDD + eg * 4];
                *(float4*)&Ks[row * 64 + ((eg ^ (row >> 3)) << 2)] = kv;
                float4 vv = *(const float4*)&vp[(size_t)(k0 + row) * HDD + eg * 4];
                *(float4*)&Vs[row * 64 + eg * 4] = vv;
            }
        }
        __syncthreads();

        // S = Q K^T  (q pre-scaled by 1/8)
        float sacc[4][8];
#pragma unroll
        for (int rr = 0; rr < 4; ++rr)
#pragma unroll
            for (int jj = 0; jj < 8; ++jj) sacc[rr][jj] = 0.0f;

#pragma unroll 2
        for (int e4 = 0; e4 < 16; ++e4) {
            float4 kf[8];
#pragma unroll
            for (int jj = 0; jj < 8; ++jj)
                kf[jj] = *(const float4*)&Ks[(jg * 8 + jj) * 64 + ((e4 ^ jg) << 2)];
#pragma unroll
            for (int rr = 0; rr < 4; ++rr) {
                int row = rowbase + rr;
                float4 qf = *(const float4*)&Qs[row * 64 + ((e4 ^ ((row >> 2) & 7)) << 2)];
#pragma unroll
                for (int jj = 0; jj < 8; ++jj) {
                    sacc[rr][jj] = fmaf(qf.x, kf[jj].x, sacc[rr][jj]);
                    sacc[rr][jj] = fmaf(qf.y, kf[jj].y, sacc[rr][jj]);
                    sacc[rr][jj] = fmaf(qf.z, kf[jj].z, sacc[rr][jj]);
                    sacc[rr][jj] = fmaf(qf.w, kf[jj].w, sacc[rr][jj]);
                }
            }
        }

        // Causal mask (only the last two tiles can be partial)
        if (kt >= 2 * qt) {
#pragma unroll
            for (int rr = 0; rr < 4; ++rr) {
                int rglob = q0 + rowbase + rr;
#pragma unroll
                for (int jj = 0; jj < 8; ++jj) {
                    int jglob = k0 + jg * 8 + jj;
                    if (jglob > rglob) sacc[rr][jj] = -1e30f;
                }
            }
        }

        // Online softmax (reduce over jg lanes: xor 1,2,4)
#pragma unroll
        for (int rr = 0; rr < 4; ++rr) {
            float mt = sacc[rr][0];
#pragma unroll
            for (int jj = 1; jj < 8; ++jj) mt = fmaxf(mt, sacc[rr][jj]);
            mt = fmaxf(mt, __shfl_xor_sync(0xffffffffu, mt, 1));
            mt = fmaxf(mt, __shfl_xor_sync(0xffffffffu, mt, 2));
            mt = fmaxf(mt, __shfl_xor_sync(0xffffffffu, mt, 4));
            float mnew = fmaxf(mrow[rr], mt);
            float corr = __expf(mrow[rr] - mnew);
            mrow[rr] = mnew;
            float ls = 0.0f;
#pragma unroll
            for (int jj = 0; jj < 8; ++jj) {
                float p = __expf(sacc[rr][jj] - mnew);
                sacc[rr][jj] = p;
                ls += p;
            }
            ls += __shfl_xor_sync(0xffffffffu, ls, 1);
            ls += __shfl_xor_sync(0xffffffffu, ls, 2);
            ls += __shfl_xor_sync(0xffffffffu, ls, 4);
            lrow[rr] = lrow[rr] * corr + ls;
#pragma unroll
            for (int ee = 0; ee < 8; ++ee) o[rr][ee] *= corr;
            int row = rowbase + rr;
#pragma unroll
            for (int jj = 0; jj < 8; ++jj) Ps[row * 65 + jg * 8 + jj] = sacc[rr][jj];
        }
        __syncwarp();

        // O += P V
#pragma unroll 8
        for (int j = 0; j < 64; ++j) {
            float4 v0 = *(const float4*)&Vs[j * 64 + jg * 8];
            float4 v1 = *(const float4*)&Vs[j * 64 + jg * 8 + 4];
            float vv[8] = {v0.x, v0.y, v0.z, v0.w, v1.x, v1.y, v1.z, v1.w};
            float pr[4];
#pragma unroll
            for (int rr = 0; rr < 4; ++rr) pr[rr] = Ps[(rowbase + rr) * 65 + j];
#pragma unroll
            for (int rr = 0; rr < 4; ++rr)
#pragma unroll
                for (int ee = 0; ee < 8; ++ee)
                    o[rr][ee] = fmaf(pr[rr], vv[ee], o[rr][ee]);
        }
    }

    // Epilogue: normalize and write [B,S,D] with heads concatenated
#pragma unroll
    for (int rr = 0; rr < 4; ++rr) {
        float inv = 1.0f / lrow[rr];
        int rglob = q0 + rowbase + rr;
        size_t ob = ((size_t)b * SS + rglob) * DD + h * HDD + jg * 8;
        float4 r0, r1;
        r0.x = o[rr][0] * inv; r0.y = o[rr][1] * inv;
        r0.z = o[rr][2] * inv; r0.w = o[rr][3] * inv;
        r1.x = o[rr][4] * inv; r1.y = o[rr][5] * inv;
        r1.z = o[rr][6] * inv; r1.w = o[rr][7] * inv;
        *(float4*)&g_o[ob]     = r0;
        *(float4*)&g_o[ob + 4] = r1;
    }
    (void)Qs;
}

// ---------------------------------------------------------------------------
// Output projection: d_out = g_o @ Wp + bp.  Same tiling as qkv_kernel.
// ---------------------------------------------------------------------------
__global__ __launch_bounds__(256, 1) void proj_kernel(
    const float* __restrict__ Wp, const float* __restrict__ bp,
    float* __restrict__ out)
{
    const int mt = blockIdx.x;  // 0..63
    const int nt = blockIdx.y;  // 0..15
    const int m0 = mt * 128, n0 = nt * 64;

    __shared__ float As[16][132];
    __shared__ float Bs[16][64];

    const int t  = threadIdx.x;
    const int tx = t & 15, ty = t >> 4;
    const int lrow = t >> 2, lkg = t & 3;

    float acc[8][4];
#pragma unroll
    for (int i = 0; i < 8; ++i)
#pragma unroll
        for (int j = 0; j < 4; ++j) acc[i][j] = 0.0f;

    for (int k0 = 0; k0 < DD; k0 += 16) {
        float4 a0 = *(const float4*)&g_o[(size_t)(m0 + lrow)      * DD + k0 + lkg * 4];
        float4 a1 = *(const float4*)&g_o[(size_t)(m0 + lrow + 64) * DD + k0 + lkg * 4];
        float4 b0 = *(const float4*)&Wp[(size_t)(k0 + ty) * DD + n0 + tx * 4];
        __syncthreads();
        As[lkg*4 + 0][lrow] = a0.x; As[lkg*4 + 1][lrow] = a0.y;
        As[lkg*4 + 2][lrow] = a0.z; As[lkg*4 + 3][lrow] = a0.w;
        As[lkg*4 + 0][lrow + 64] = a1.x; As[lkg*4 + 1][lrow + 64] = a1.y;
        As[lkg*4 + 2][lrow + 64] = a1.z; As[lkg*4 + 3][lrow + 64] = a1.w;
        *(float4*)&Bs[ty][tx * 4] = b0;
        __syncthreads();
#pragma unroll
        for (int kk = 0; kk < 16; ++kk) {
            float4 a04 = *(const float4*)&As[kk][ty * 8];
            float4 a14 = *(const float4*)&As[kk][ty * 8 + 4];
            float4 bv4 = *(const float4*)&Bs[kk][tx * 4];
            float av[8] = {a04.x, a04.y, a04.z, a04.w, a14.x, a14.y, a14.z, a14.w};
            float bv_[4] = {bv4.x, bv4.y, bv4.z, bv4.w};
#pragma unroll
            for (int i = 0; i < 8; ++i)
#pragma unroll
                for (int j = 0; j < 4; ++j)
                    acc[i][j] = fmaf(av[i], bv_[j], acc[i][j]);
        }
    }

    float bb[4];
#pragma unroll
    for (int j = 0; j < 4; ++j) bb[j] = bp[n0 + tx * 4 + j];
#pragma unroll
    for (int i = 0; i < 8; ++i) {
        int r = m0 + ty * 8 + i;
        float4 v;
        v.x = acc[i][0] + bb[0];
        v.y = acc[i][1] + bb[1];
        v.z = acc[i][2] + bb[2];
        v.w = acc[i][3] + bb[3];
        *(float4*)&out[(size_t)r * DD + n0 + tx * 4] = v;
    }
}

// ---------------------------------------------------------------------------
extern "C" void kernel_launch(void* const* d_in, const int* in_sizes, int n_in,
                              void* d_out, int out_size)
{
    const float* x  = (const float*)d_in[0];
    const float* Wq = (const float*)d_in[1];
    const float* bq = (const float*)d_in[2];
    const float* Wk = (const float*)d_in[3];
    const float* bk = (const float*)d_in[4];
    const float* Wv = (const float*)d_in[5];
    const float* bv = (const float*)d_in[6];
    const float* Wp = (const float*)d_in[7];
    const float* bp = (const float*)d_in[8];
    float* out = (float*)d_out;

    const int attn_smem = ATTN_SMEM_FLOATS * (int)sizeof(float);  // 98816 B
    cudaFuncSetAttribute(attn_kernel,
                         cudaFuncAttributeMaxDynamicSharedMemorySize, attn_smem);

    qkv_kernel<<<dim3(64, 16, 3), 256>>>(x, Wq, bq, Wk, bk, Wv, bv);
    attn_kernel<<<dim3(16, 16, 4), 256, attn_smem>>>();
    proj_kernel<<<dim3(64, 16, 1), 256>>>(Wp, bp, out);

    (void)in_sizes; (void)n_in; (void)out_size;
}

// round 6
// speedup vs baseline: 1.2414x; 1.2414x over previous
#include <cuda_runtime.h>
#include <cuda_bf16.h>
#include <cstdint>

#define BB 4
#define SS 2048
#define DD 1024
#define HH 16
#define HDD 64
#define NTOK (BB*SS)

// ---------------- scratch ----------------
__device__ float g_q[BB*HH*SS*HDD];
__device__ float g_k[BB*HH*SS*HDD];
__device__ float g_v[BB*HH*SS*HDD];
__device__ float g_o[NTOK*DD];

__device__ __nv_bfloat16 g_xhi[NTOK*DD];
__device__ __nv_bfloat16 g_xlo[NTOK*DD];
__device__ __nv_bfloat16 g_wqkv_hi[3*DD*DD];   // [n=3072][k=1024]
__device__ __nv_bfloat16 g_wqkv_lo[3*DD*DD];
__device__ float g_biascat[3*DD];

// ---------------- helpers ----------------
static __device__ __forceinline__ uint32_t smem_u32(const void* p) {
    uint32_t a;
    asm("{ .reg .u64 t; cvta.to.shared.u64 t, %1; cvt.u32.u64 %0, t; }"
        : "=r"(a) : "l"(p));
    return a;
}

static __device__ __forceinline__ void cp16(uint32_t dst, const void* src) {
    asm volatile("cp.async.cg.shared.global [%0], [%1], 16;" :: "r"(dst), "l"(src));
}
#define CP_COMMIT() asm volatile("cp.async.commit_group;" ::: "memory")
#define CP_WAIT1()  asm volatile("cp.async.wait_group 1;" ::: "memory")
#define CP_WAIT0()  asm volatile("cp.async.wait_group 0;" ::: "memory")

static __device__ __forceinline__ void ldm_x4(uint32_t* r, uint32_t addr) {
    asm volatile("ldmatrix.sync.aligned.m8n8.x4.shared.b16 {%0,%1,%2,%3}, [%4];"
                 : "=r"(r[0]), "=r"(r[1]), "=r"(r[2]), "=r"(r[3]) : "r"(addr));
}

static __device__ __forceinline__ void mma16816(float* d, const uint32_t* a,
                                                const uint32_t* b) {
    asm volatile(
        "mma.sync.aligned.m16n8k16.row.col.f32.bf16.bf16.f32 "
        "{%0,%1,%2,%3}, {%4,%5,%6,%7}, {%8,%9}, {%0,%1,%2,%3};"
        : "+f"(d[0]), "+f"(d[1]), "+f"(d[2]), "+f"(d[3])
        : "r"(a[0]), "r"(a[1]), "r"(a[2]), "r"(a[3]), "r"(b[0]), "r"(b[1]));
}

// ---------------- conversion kernels ----------------
__global__ __launch_bounds__(256) void cvt_x_kernel(const float* __restrict__ x)
{
    int idx = blockIdx.x * 256 + threadIdx.x;     // 4 elems each
    float4 v = *(const float4*)(x + (size_t)idx * 4);
    __nv_bfloat16 h0 = __float2bfloat16(v.x), h1 = __float2bfloat16(v.y);
    __nv_bfloat16 h2 = __float2bfloat16(v.z), h3 = __float2bfloat16(v.w);
    __nv_bfloat16 l0 = __float2bfloat16(v.x - __bfloat162float(h0));
    __nv_bfloat16 l1 = __float2bfloat16(v.y - __bfloat162float(h1));
    __nv_bfloat16 l2 = __float2bfloat16(v.z - __bfloat162float(h2));
    __nv_bfloat16 l3 = __float2bfloat16(v.w - __bfloat162float(h3));
    __nv_bfloat162* hp = (__nv_bfloat162*)g_xhi;
    __nv_bfloat162* lp = (__nv_bfloat162*)g_xlo;
    hp[idx * 2]     = __nv_bfloat162(h0, h1);
    hp[idx * 2 + 1] = __nv_bfloat162(h2, h3);
    lp[idx * 2]     = __nv_bfloat162(l0, l1);
    lp[idx * 2 + 1] = __nv_bfloat162(l2, l3);
}

// Wcat[n][k] = W[which][h][k][e], n = which*1024 + h*64 + e. Also biascat.
__global__ __launch_bounds__(256) void cvt_wqkv_kernel(
    const float* __restrict__ Wq, const float* __restrict__ Wk,
    const float* __restrict__ Wv, const float* __restrict__ bq,
    const float* __restrict__ bk, const float* __restrict__ bv)
{
    int gid = blockIdx.x * 256 + threadIdx.x;     // 3072 * 128
    int n = gid >> 7;
    int k0 = (gid & 127) << 3;
    int which = n >> 10, h = (n >> 6) & 15, e = n & 63;
    const float* W = which == 0 ? Wq : (which == 1 ? Wk : Wv);
    const float* base = W + (size_t)h * DD * HDD + e;
#pragma unroll
    for (int i = 0; i < 8; ++i) {
        float x = base[(size_t)(k0 + i) * HDD];
        __nv_bfloat16 hi = __float2bfloat16(x);
        __nv_bfloat16 lo = __float2bfloat16(x - __bfloat162float(hi));
        g_wqkv_hi[(size_t)n * DD + k0 + i] = hi;
        g_wqkv_lo[(size_t)n * DD + k0 + i] = lo;
    }
    if (k0 == 0) {
        const float* bb = which == 0 ? bq : (which == 1 ? bk : bv);
        g_biascat[n] = bb[h * HDD + e];
    }
}

// ---------------- mma.sync QKV GEMM ----------------
// C[m][n] = x·Wcat^T over virtual K' = 3072:
//   phase 0: xhi·Whi, phase 1: xhi·Wlo, phase 2: xlo·Whi  (bf16x3)
// BM=128, BN=128, BK=64, 256 thr (8 warps, 2x4), warp tile 64x32.
#define G_STG   32768u
#define G_SMEM  (2 * 32768)
#define G_NCH   48

static __device__ __forceinline__ void g_load(
    uint32_t sA, uint32_t sB,
    const __nv_bfloat16* __restrict__ Asrc, const __nv_bfloat16* __restrict__ Bsrc,
    int m0, int n0, int kk, int t)
{
#pragma unroll
    for (int i = 0; i < 4; ++i) {
        int idx = t + i * 256;
        int row = idx >> 3, c = idx & 7;
        cp16(sA + row * 128 + (((c ^ (row & 7)) & 7) << 4),
             Asrc + (size_t)(m0 + row) * DD + kk + c * 8);
    }
#pragma unroll
    for (int i = 0; i < 4; ++i) {
        int idx = t + i * 256;
        int row = idx >> 3, c = idx & 7;
        cp16(sB + row * 128 + (((c ^ (row & 7)) & 7) << 4),
             Bsrc + (size_t)(n0 + row) * DD + kk + c * 8);
    }
}

__global__ __launch_bounds__(256, 1) void qkv_mma_kernel()
{
    extern __shared__ char smem[];
    const uint32_t sb = smem_u32(smem);
    const int t = threadIdx.x, wid = t >> 5, lane = t & 31;
    const int warp_m = wid & 1, warp_n = wid >> 1;
    const int m0 = blockIdx.x * 128, n0 = blockIdx.y * 128;

    float acc[4][4][4];
#pragma unroll
    for (int i = 0; i < 4; ++i)
#pragma unroll
        for (int j = 0; j < 4; ++j)
#pragma unroll
            for (int e = 0; e < 4; ++e) acc[i][j][e] = 0.0f;

    const int a_row = (lane & 7) + ((lane >> 3) & 1) * 8;
    const int a_kch = lane >> 4;
    const int b_nof = (lane & 7) + ((lane >> 4) & 1) * 8;
    const int b_kch = (lane >> 3) & 1;

#define ASRC(c) (((c) >> 4) < 2 ? g_xhi : g_xlo)
#define BSRC(c) ((((c) >> 4) == 1) ? g_wqkv_lo : g_wqkv_hi)

    g_load(sb,         sb + 16384u,          ASRC(0), BSRC(0), m0, n0, 0,  t);
    CP_COMMIT();
    g_load(sb + G_STG, sb + G_STG + 16384u,  ASRC(1), BSRC(1), m0, n0, 64, t);
    CP_COMMIT();

    for (int c = 0; c < G_NCH; ++c) {
        const uint32_t sA = sb + (c & 1) * G_STG;
        const uint32_t sB = sA + 16384u;
        CP_WAIT1();
        __syncthreads();

#pragma unroll
        for (int ks = 0; ks < 4; ++ks) {
            uint32_t afr[4][4];
#pragma unroll
            for (int mt = 0; mt < 4; ++mt) {
                int r = warp_m * 64 + mt * 16 + a_row;
                int ch = ks * 2 + a_kch;
                ldm_x4(afr[mt], sA + r * 128 + (((ch ^ (r & 7)) & 7) << 4));
            }
            uint32_t bfr[2][4];
#pragma unroll
            for (int g = 0; g < 2; ++g) {
                int r = warp_n * 32 + g * 16 + b_nof;
                int ch = ks * 2 + b_kch;
                ldm_x4(bfr[g], sB + r * 128 + (((ch ^ (r & 7)) & 7) << 4));
            }
#pragma unroll
            for (int mt = 0; mt < 4; ++mt)
#pragma unroll
                for (int nt = 0; nt < 4; ++nt)
                    mma16816(acc[mt][nt], afr[mt], &bfr[nt >> 1][(nt & 1) * 2]);
        }

        __syncthreads();
        if (c + 2 < G_NCH) {
            int cn = c + 2;
            g_load(sA, sB, ASRC(cn), BSRC(cn), m0, n0, (cn & 15) * 64, t);
        }
        CP_COMMIT();   // uniform bookkeeping (empty groups complete immediately)
    }
    CP_WAIT0();

    // Epilogue: scatter to g_q/g_k/g_v [B,H,S,HD]
#pragma unroll
    for (int mt = 0; mt < 4; ++mt) {
#pragma unroll
        for (int nt = 0; nt < 4; ++nt) {
            int r0 = m0 + warp_m * 64 + mt * 16 + (lane >> 2);
            int c0 = n0 + warp_n * 32 + nt * 8 + (lane & 3) * 2;
#pragma unroll
            for (int half = 0; half < 2; ++half) {
                int r = r0 + half * 8;
                float v0 = acc[mt][nt][half * 2 + 0];
                float v1 = acc[mt][nt][half * 2 + 1];
                int which = c0 >> 10, h = (c0 >> 6) & 15, e = c0 & 63;
                float scl = which == 0 ? 0.125f : 1.0f;
                float* dst = which == 0 ? g_q : (which == 1 ? g_k : g_v);
                int b = r >> 11, s_ = r & (SS - 1);
                size_t off = (((size_t)(b * HH + h)) * SS + s_) * HDD + e;
                float2 w;
                w.x = (v0 + g_biascat[c0])     * scl;
                w.y = (v1 + g_biascat[c0 + 1]) * scl;
                *(float2*)&dst[off] = w;
            }
        }
    }
}

// ---------------------------------------------------------------------------
// Flash attention (causal), fp32 — bit-identical to round 1 (known good).
// ---------------------------------------------------------------------------
#define ATTN_SMEM_FLOATS (128*64 + 64*64 + 64*64 + 128*65)

__global__ __launch_bounds__(256, 1) void attn_kernel()
{
    extern __shared__ float sm[];
    float* Qs = sm;
    float* Ks = sm + 8192;
    float* Vs = sm + 12288;
    float* Ps = sm + 16384;

    const int qt = blockIdx.x;
    const int h  = blockIdx.y;
    const int b  = blockIdx.z;
    const int q0 = qt * 128;

    const int t    = threadIdx.x;
    const int w    = t >> 5;
    const int lane = t & 31;
    const int jg   = lane & 7;
    const int rg   = lane >> 3;
    const int rowbase = w * 16 + rg * 4;

    const size_t base = ((size_t)(b * HH + h)) * SS * HDD;
    const float* qp = g_q + base;
    const float* kp = g_k + base;
    const float* vp = g_v + base;

    {
        int row = t >> 4, eg = t & 15;
#pragma unroll
        for (int it = 0; it < 8; ++it, row += 16) {
            float4 qv = *(const float4*)&qp[(size_t)(q0 + row) * HDD + eg * 4];
            *(float4*)&Qs[row * 64 + ((eg ^ ((row >> 2) & 7)) << 2)] = qv;
        }
    }

    float o[4][8];
    float mrow[4], lrow[4];
#pragma unroll
    for (int rr = 0; rr < 4; ++rr) {
        mrow[rr] = -1e30f; lrow[rr] = 0.0f;
#pragma unroll
        for (int ee = 0; ee < 8; ++ee) o[rr][ee] = 0.0f;
    }

    const int nkt = qt * 2 + 2;
    for (int kt = 0; kt < nkt; ++kt) {
        const int k0 = kt * 64;
        __syncthreads();
        {
            int row = t >> 4, eg = t & 15;
#pragma unroll
            for (int it = 0; it < 4; ++it, row += 16) {
                float4 kv = *(const float4*)&kp[(size_t)(k0 + row) * HDD + eg * 4];
                *(float4*)&Ks[row * 64 + ((eg ^ (row >> 3)) << 2)] = kv;
                float4 vv = *(const float4*)&vp[(size_t)(k0 + row) * HDD + eg * 4];
                *(float4*)&Vs[row * 64 + eg * 4] = vv;
            }
        }
        __syncthreads();

        float sacc[4][8];
#pragma unroll
        for (int rr = 0; rr < 4; ++rr)
#pragma unroll
            for (int jj = 0; jj < 8; ++jj) sacc[rr][jj] = 0.0f;

#pragma unroll 2
        for (int e4 = 0; e4 < 16; ++e4) {
            float4 kf[8];
#pragma unroll
            for (int jj = 0; jj < 8; ++jj)
                kf[jj] = *(const float4*)&Ks[(jg * 8 + jj) * 64 + ((e4 ^ jg) << 2)];
#pragma unroll
            for (int rr = 0; rr < 4; ++rr) {
                int row = rowbase + rr;
                float4 qf = *(const float4*)&Qs[row * 64 + ((e4 ^ ((row >> 2) & 7)) << 2)];
#pragma unroll
                for (int jj = 0; jj < 8; ++jj) {
                    sacc[rr][jj] = fmaf(qf.x, kf[jj].x, sacc[rr][jj]);
                    sacc[rr][jj] = fmaf(qf.y, kf[jj].y, sacc[rr][jj]);
                    sacc[rr][jj] = fmaf(qf.z, kf[jj].z, sacc[rr][jj]);
                    sacc[rr][jj] = fmaf(qf.w, kf[jj].w, sacc[rr][jj]);
                }
            }
        }

        if (kt >= 2 * qt) {
#pragma unroll
            for (int rr = 0; rr < 4; ++rr) {
                int rglob = q0 + rowbase + rr;
#pragma unroll
                for (int jj = 0; jj < 8; ++jj) {
                    int jglob = k0 + jg * 8 + jj;
                    if (jglob > rglob) sacc[rr][jj] = -1e30f;
                }
            }
        }

#pragma unroll
        for (int rr = 0; rr < 4; ++rr) {
            float mt = sacc[rr][0];
#pragma unroll
            for (int jj = 1; jj < 8; ++jj) mt = fmaxf(mt, sacc[rr][jj]);
            mt = fmaxf(mt, __shfl_xor_sync(0xffffffffu, mt, 1));
            mt = fmaxf(mt, __shfl_xor_sync(0xffffffffu, mt, 2));
            mt = fmaxf(mt, __shfl_xor_sync(0xffffffffu, mt, 4));
            float mnew = fmaxf(mrow[rr], mt);
            float corr = __expf(mrow[rr] - mnew);
            mrow[rr] = mnew;
            float ls = 0.0f;
#pragma unroll
            for (int jj = 0; jj < 8; ++jj) {
                float p = __expf(sacc[rr][jj] - mnew);
                sacc[rr][jj] = p;
                ls += p;
            }
            ls += __shfl_xor_sync(0xffffffffu, ls, 1);
            ls += __shfl_xor_sync(0xffffffffu, ls, 2);
            ls += __shfl_xor_sync(0xffffffffu, ls, 4);
            lrow[rr] = lrow[rr] * corr + ls;
#pragma unroll
            for (int ee = 0; ee < 8; ++ee) o[rr][ee] *= corr;
            int row = rowbase + rr;
#pragma unroll
            for (int jj = 0; jj < 8; ++jj) Ps[row * 65 + jg * 8 + jj] = sacc[rr][jj];
        }
        __syncwarp();

#pragma unroll 8
        for (int j = 0; j < 64; ++j) {
            float4 v0 = *(const float4*)&Vs[j * 64 + jg * 8];
            float4 v1 = *(const float4*)&Vs[j * 64 + jg * 8 + 4];
            float vv[8] = {v0.x, v0.y, v0.z, v0.w, v1.x, v1.y, v1.z, v1.w};
            float pr[4];
#pragma unroll
            for (int rr = 0; rr < 4; ++rr) pr[rr] = Ps[(rowbase + rr) * 65 + j];
#pragma unroll
            for (int rr = 0; rr < 4; ++rr)
#pragma unroll
                for (int ee = 0; ee < 8; ++ee)
                    o[rr][ee] = fmaf(pr[rr], vv[ee], o[rr][ee]);
        }
    }

#pragma unroll
    for (int rr = 0; rr < 4; ++rr) {
        float inv = 1.0f / lrow[rr];
        int rglob = q0 + rowbase + rr;
        size_t ob = ((size_t)b * SS + rglob) * DD + h * HDD + jg * 8;
        float4 r0, r1;
        r0.x = o[rr][0] * inv; r0.y = o[rr][1] * inv;
        r0.z = o[rr][2] * inv; r0.w = o[rr][3] * inv;
        r1.x = o[rr][4] * inv; r1.y = o[rr][5] * inv;
        r1.z = o[rr][6] * inv; r1.w = o[rr][7] * inv;
        *(float4*)&g_o[ob]     = r0;
        *(float4*)&g_o[ob + 4] = r1;
    }
    (void)Qs;
}

// ---------------------------------------------------------------------------
// Output projection: d_out = g_o @ Wp + bp — bit-identical to round 1.
// ---------------------------------------------------------------------------
__global__ __launch_bounds__(256, 1) void proj_kernel(
    const float* __restrict__ Wp, const float* __restrict__ bp,
    float* __restrict__ out)
{
    const int mt = blockIdx.x;  // 0..63
    const int nt = blockIdx.y;  // 0..15
    const int m0 = mt * 128, n0 = nt * 64;

    __shared__ float As[16][132];
    __shared__ float Bs[16][64];

    const int t  = threadIdx.x;
    const int tx = t & 15, ty = t >> 4;
    const int lrow = t >> 2, lkg = t & 3;

    float acc[8][4];
#pragma unroll
    for (int i = 0; i < 8; ++i)
#pragma unroll
        for (int j = 0; j < 4; ++j) acc[i][j] = 0.0f;

    for (int k0 = 0; k0 < DD; k0 += 16) {
        float4 a0 = *(const float4*)&g_o[(size_t)(m0 + lrow)      * DD + k0 + lkg * 4];
        float4 a1 = *(const float4*)&g_o[(size_t)(m0 + lrow + 64) * DD + k0 + lkg * 4];
        float4 b0 = *(const float4*)&Wp[(size_t)(k0 + ty) * DD + n0 + tx * 4];
        __syncthreads();
        As[lkg*4 + 0][lrow] = a0.x; As[lkg*4 + 1][lrow] = a0.y;
        As[lkg*4 + 2][lrow] = a0.z; As[lkg*4 + 3][lrow] = a0.w;
        As[lkg*4 + 0][lrow + 64] = a1.x; As[lkg*4 + 1][lrow + 64] = a1.y;
        As[lkg*4 + 2][lrow + 64] = a1.z; As[lkg*4 + 3][lrow + 64] = a1.w;
        *(float4*)&Bs[ty][tx * 4] = b0;
        __syncthreads();
#pragma unroll
        for (int kk = 0; kk < 16; ++kk) {
            float4 a04 = *(const float4*)&As[kk][ty * 8];
            float4 a14 = *(const float4*)&As[kk][ty * 8 + 4];
            float4 bv4 = *(const float4*)&Bs[kk][tx * 4];
            float av[8] = {a04.x, a04.y, a04.z, a04.w, a14.x, a14.y, a14.z, a14.w};
            float bv_[4] = {bv4.x, bv4.y, bv4.z, bv4.w};
#pragma unroll
            for (int i = 0; i < 8; ++i)
#pragma unroll
                for (int j = 0; j < 4; ++j)
                    acc[i][j] = fmaf(av[i], bv_[j], acc[i][j]);
        }
    }

    float bb[4];
#pragma unroll
    for (int j = 0; j < 4; ++j) bb[j] = bp[n0 + tx * 4 + j];
#pragma unroll
    for (int i = 0; i < 8; ++i) {
        int r = m0 + ty * 8 + i;
        float4 v;
        v.x = acc[i][0] + bb[0];
        v.y = acc[i][1] + bb[1];
        v.z = acc[i][2] + bb[2];
        v.w = acc[i][3] + bb[3];
        *(float4*)&out[(size_t)r * DD + n0 + tx * 4] = v;
    }
}

// ---------------------------------------------------------------------------
extern "C" void kernel_launch(void* const* d_in, const int* in_sizes, int n_in,
                              void* d_out, int out_size)
{
    const float* x  = (const float*)d_in[0];
    const float* Wq = (const float*)d_in[1];
    const float* bq = (const float*)d_in[2];
    const float* Wk = (const float*)d_in[3];
    const float* bk = (const float*)d_in[4];
    const float* Wv = (const float*)d_in[5];
    const float* bv = (const float*)d_in[6];
    const float* Wp = (const float*)d_in[7];
    const float* bp = (const float*)d_in[8];
    float* out = (float*)d_out;

    const int attn_smem = ATTN_SMEM_FLOATS * (int)sizeof(float);
    cudaFuncSetAttribute(attn_kernel,
                         cudaFuncAttributeMaxDynamicSharedMemorySize, attn_smem);
    cudaFuncSetAttribute(qkv_mma_kernel,
                         cudaFuncAttributeMaxDynamicSharedMemorySize, G_SMEM);

    cvt_x_kernel<<<NTOK * DD / 1024, 256>>>(x);
    cvt_wqkv_kernel<<<3 * DD * 128 / 256, 256>>>(Wq, Wk, Wv, bq, bk, bv);

    qkv_mma_kernel<<<dim3(64, 24), 256, G_SMEM>>>();

    attn_kernel<<<dim3(16, 16, 4), 256, attn_smem>>>();

    proj_kernel<<<dim3(64, 16, 1), 256>>>(Wp, bp, out);

    (void)in_sizes; (void)n_in; (void)out_size;
}

// round 7
// speedup vs baseline: 2.0783x; 1.6741x over previous
#include <cuda_runtime.h>
#include <cuda_bf16.h>
#include <cstdint>

#define BB 4
#define SS 2048
#define DD 1024
#define HH 16
#define HDD 64
#define NTOK (BB*SS)

// ---------------- scratch ----------------
__device__ float g_o[NTOK*DD];

__device__ __nv_bfloat16 g_qhi[BB*HH*SS*HDD];   // [bh][s][hd], pre-scaled by 0.125*log2e
__device__ __nv_bfloat16 g_qlo[BB*HH*SS*HDD];
__device__ __nv_bfloat16 g_khi[BB*HH*SS*HDD];   // [bh][s][hd]
__device__ __nv_bfloat16 g_klo[BB*HH*SS*HDD];
__device__ __nv_bfloat16 g_vthi[BB*HH*HDD*SS];  // [bh][hd][s]  (transposed V)
__device__ __nv_bfloat16 g_vtlo[BB*HH*HDD*SS];

__device__ __nv_bfloat16 g_xhi[NTOK*DD];
__device__ __nv_bfloat16 g_xlo[NTOK*DD];
__device__ __nv_bfloat16 g_wqkv_hi[3*DD*DD];    // [n=3072][k=1024]
__device__ __nv_bfloat16 g_wqkv_lo[3*DD*DD];
__device__ float g_biascat[3*DD];

// ---------------- helpers ----------------
static __device__ __forceinline__ uint32_t smem_u32(const void* p) {
    uint32_t a;
    asm("{ .reg .u64 t; cvta.to.shared.u64 t, %1; cvt.u32.u64 %0, t; }"
        : "=r"(a) : "l"(p));
    return a;
}

static __device__ __forceinline__ void cp16(uint32_t dst, const void* src) {
    asm volatile("cp.async.cg.shared.global [%0], [%1], 16;" :: "r"(dst), "l"(src));
}
#define CP_COMMIT() asm volatile("cp.async.commit_group;" ::: "memory")
#define CP_WAIT1()  asm volatile("cp.async.wait_group 1;" ::: "memory")
#define CP_WAIT0()  asm volatile("cp.async.wait_group 0;" ::: "memory")

static __device__ __forceinline__ void ldm_x4(uint32_t* r, uint32_t addr) {
    asm volatile("ldmatrix.sync.aligned.m8n8.x4.shared.b16 {%0,%1,%2,%3}, [%4];"
                 : "=r"(r[0]), "=r"(r[1]), "=r"(r[2]), "=r"(r[3]) : "r"(addr));
}

static __device__ __forceinline__ void mma16816(float* d, const uint32_t* a,
                                                const uint32_t* b) {
    asm volatile(
        "mma.sync.aligned.m16n8k16.row.col.f32.bf16.bf16.f32 "
        "{%0,%1,%2,%3}, {%4,%5,%6,%7}, {%8,%9}, {%0,%1,%2,%3};"
        : "+f"(d[0]), "+f"(d[1]), "+f"(d[2]), "+f"(d[3])
        : "r"(a[0]), "r"(a[1]), "r"(a[2]), "r"(a[3]), "r"(b[0]), "r"(b[1]));
}

// 2^t via FMA-pipe polynomial (deg-5 Taylor, rel err <= ~1e-4); t <= 0 expected.
static __device__ __forceinline__ float exp2p(float t) {
    t = fmaxf(t, -126.0f);
    float n = floorf(t);
    float f = t - n;
    float p = 1.33333642e-3f;
    p = fmaf(p, f, 9.61812910e-3f);
    p = fmaf(p, f, 5.55041087e-2f);
    p = fmaf(p, f, 2.40226507e-1f);
    p = fmaf(p, f, 6.93147181e-1f);
    p = fmaf(p, f, 1.0f);
    return p * __int_as_float(((int)n + 127) << 23);
}

// ---------------- conversion kernels ----------------
__global__ __launch_bounds__(256) void cvt_x_kernel(const float* __restrict__ x)
{
    int idx = blockIdx.x * 256 + threadIdx.x;     // 4 elems each
    float4 v = *(const float4*)(x + (size_t)idx * 4);
    __nv_bfloat16 h0 = __float2bfloat16(v.x), h1 = __float2bfloat16(v.y);
    __nv_bfloat16 h2 = __float2bfloat16(v.z), h3 = __float2bfloat16(v.w);
    __nv_bfloat16 l0 = __float2bfloat16(v.x - __bfloat162float(h0));
    __nv_bfloat16 l1 = __float2bfloat16(v.y - __bfloat162float(h1));
    __nv_bfloat16 l2 = __float2bfloat16(v.z - __bfloat162float(h2));
    __nv_bfloat16 l3 = __float2bfloat16(v.w - __bfloat162float(h3));
    __nv_bfloat162* hp = (__nv_bfloat162*)g_xhi;
    __nv_bfloat162* lp = (__nv_bfloat162*)g_xlo;
    hp[idx * 2]     = __nv_bfloat162(h0, h1);
    hp[idx * 2 + 1] = __nv_bfloat162(h2, h3);
    lp[idx * 2]     = __nv_bfloat162(l0, l1);
    lp[idx * 2 + 1] = __nv_bfloat162(l2, l3);
}

// Wcat[n][k] = W[which][h][k][e], n = which*1024 + h*64 + e. Also biascat.
__global__ __launch_bounds__(256) void cvt_wqkv_kernel(
    const float* __restrict__ Wq, const float* __restrict__ Wk,
    const float* __restrict__ Wv, const float* __restrict__ bq,
    const float* __restrict__ bk, const float* __restrict__ bv)
{
    int gid = blockIdx.x * 256 + threadIdx.x;     // 3072 * 128
    int n = gid >> 7;
    int k0 = (gid & 127) << 3;
    int which = n >> 10, h = (n >> 6) & 15, e = n & 63;
    const float* W = which == 0 ? Wq : (which == 1 ? Wk : Wv);
    const float* base = W + (size_t)h * DD * HDD + e;
#pragma unroll
    for (int i = 0; i < 8; ++i) {
        float x = base[(size_t)(k0 + i) * HDD];
        __nv_bfloat16 hi = __float2bfloat16(x);
        __nv_bfloat16 lo = __float2bfloat16(x - __bfloat162float(hi));
        g_wqkv_hi[(size_t)n * DD + k0 + i] = hi;
        g_wqkv_lo[(size_t)n * DD + k0 + i] = lo;
    }
    if (k0 == 0) {
        const float* bb = which == 0 ? bq : (which == 1 ? bk : bv);
        g_biascat[n] = bb[h * HDD + e];
    }
}

// ---------------- mma.sync QKV GEMM (mainloop proven in round 6) ----------------
#define G_STG   32768u
#define G_SMEM  (2 * 32768)
#define G_NCH   48

static __device__ __forceinline__ void g_load(
    uint32_t sA, uint32_t sB,
    const __nv_bfloat16* __restrict__ Asrc, const __nv_bfloat16* __restrict__ Bsrc,
    int m0, int n0, int kk, int t)
{
#pragma unroll
    for (int i = 0; i < 4; ++i) {
        int idx = t + i * 256;
        int row = idx >> 3, c = idx & 7;
        cp16(sA + row * 128 + (((c ^ (row & 7)) & 7) << 4),
             Asrc + (size_t)(m0 + row) * DD + kk + c * 8);
    }
#pragma unroll
    for (int i = 0; i < 4; ++i) {
        int idx = t + i * 256;
        int row = idx >> 3, c = idx & 7;
        cp16(sB + row * 128 + (((c ^ (row & 7)) & 7) << 4),
             Bsrc + (size_t)(n0 + row) * DD + kk + c * 8);
    }
}

__global__ __launch_bounds__(256, 1) void qkv_mma_kernel()
{
    extern __shared__ char smem[];
    const uint32_t sb = smem_u32(smem);
    const int t = threadIdx.x, wid = t >> 5, lane = t & 31;
    const int warp_m = wid & 1, warp_n = wid >> 1;
    const int m0 = blockIdx.x * 128, n0 = blockIdx.y * 128;

    float acc[4][4][4];
#pragma unroll
    for (int i = 0; i < 4; ++i)
#pragma unroll
        for (int j = 0; j < 4; ++j)
#pragma unroll
            for (int e = 0; e < 4; ++e) acc[i][j][e] = 0.0f;

    const int a_row = (lane & 7) + ((lane >> 3) & 1) * 8;
    const int a_kch = lane >> 4;
    const int b_nof = (lane & 7) + ((lane >> 4) & 1) * 8;
    const int b_kch = (lane >> 3) & 1;

#define ASRC(c) (((c) >> 4) < 2 ? g_xhi : g_xlo)
#define BSRC(c) ((((c) >> 4) == 1) ? g_wqkv_lo : g_wqkv_hi)

    g_load(sb,         sb + 16384u,          ASRC(0), BSRC(0), m0, n0, 0,  t);
    CP_COMMIT();
    g_load(sb + G_STG, sb + G_STG + 16384u,  ASRC(1), BSRC(1), m0, n0, 64, t);
    CP_COMMIT();

    for (int c = 0; c < G_NCH; ++c) {
        const uint32_t sA = sb + (c & 1) * G_STG;
        const uint32_t sB = sA + 16384u;
        CP_WAIT1();
        __syncthreads();

#pragma unroll
        for (int ks = 0; ks < 4; ++ks) {
            uint32_t afr[4][4];
#pragma unroll
            for (int mt = 0; mt < 4; ++mt) {
                int r = warp_m * 64 + mt * 16 + a_row;
                int ch = ks * 2 + a_kch;
                ldm_x4(afr[mt], sA + r * 128 + (((ch ^ (r & 7)) & 7) << 4));
            }
            uint32_t bfr[2][4];
#pragma unroll
            for (int g = 0; g < 2; ++g) {
                int r = warp_n * 32 + g * 16 + b_nof;
                int ch = ks * 2 + b_kch;
                ldm_x4(bfr[g], sB + r * 128 + (((ch ^ (r & 7)) & 7) << 4));
            }
#pragma unroll
            for (int mt = 0; mt < 4; ++mt)
#pragma unroll
                for (int nt = 0; nt < 4; ++nt)
                    mma16816(acc[mt][nt], afr[mt], &bfr[nt >> 1][(nt & 1) * 2]);
        }

        __syncthreads();
        if (c + 2 < G_NCH) {
            int cn = c + 2;
            g_load(sA, sB, ASRC(cn), BSRC(cn), m0, n0, (cn & 15) * 64, t);
        }
        CP_COMMIT();
    }
    CP_WAIT0();

    // Epilogue: bf16 hi/lo scatter. Q scaled by 0.125*log2(e); V transposed.
#pragma unroll
    for (int mt = 0; mt < 4; ++mt) {
#pragma unroll
        for (int nt = 0; nt < 4; ++nt) {
            int r0 = m0 + warp_m * 64 + mt * 16 + (lane >> 2);
            int c0 = n0 + warp_n * 32 + nt * 8 + (lane & 3) * 2;
            int which = c0 >> 10, hh2 = (c0 >> 6) & 15, e = c0 & 63;
            float scl = (which == 0) ? 0.18033688f : 1.0f;   // 0.125*log2(e)
#pragma unroll
            for (int half = 0; half < 2; ++half) {
                int r = r0 + half * 8;
                float y0 = (acc[mt][nt][half*2+0] + g_biascat[c0])     * scl;
                float y1 = (acc[mt][nt][half*2+1] + g_biascat[c0 + 1]) * scl;
                __nv_bfloat16 h0 = __float2bfloat16(y0), h1 = __float2bfloat16(y1);
                __nv_bfloat16 lo0 = __float2bfloat16(y0 - __bfloat162float(h0));
                __nv_bfloat16 lo1 = __float2bfloat16(y1 - __bfloat162float(h1));
                int bb2 = r >> 11, s_ = r & (SS - 1);
                int bh = bb2 * HH + hh2;
                if (which == 2) {
                    size_t off = ((size_t)bh * HDD + e) * SS + s_;
                    g_vthi[off]      = h0;  g_vthi[off + SS] = h1;
                    g_vtlo[off]      = lo0; g_vtlo[off + SS] = lo1;
                } else {
                    size_t off = ((size_t)bh * SS + s_) * HDD + e;
                    __nv_bfloat162 H; H.x = h0;  H.y = h1;
                    __nv_bfloat162 L; L.x = lo0; L.y = lo1;
                    __nv_bfloat16* dh = which == 0 ? g_qhi : g_khi;
                    __nv_bfloat16* dl = which == 0 ? g_qlo : g_klo;
                    *reinterpret_cast<__nv_bfloat162*>(dh + off) = H;
                    *reinterpret_cast<__nv_bfloat162*>(dl + off) = L;
                }
            }
        }
    }
}

// ---------------- mma.sync flash attention ----------------
// Block: 128 q-rows x one (h,b). 8 warps, warp = 16 rows. K-tiles of 64.
// SMEM stage (32KB): Khi 8K | Klo 8K | Vthi 8K | Vtlo 8K.  Double-buffered.
#define A_STG  32768u
#define A_SMEM (2 * 32768)

static __device__ __forceinline__ void attn_load(
    uint32_t ss, const __nv_bfloat16* __restrict__ khi,
    const __nv_bfloat16* __restrict__ klo,
    const __nv_bfloat16* __restrict__ vthi,
    const __nv_bfloat16* __restrict__ vtlo, int k0, int t)
{
#pragma unroll
    for (int i = 0; i < 2; ++i) {
        int idx = t + i * 256;           // [0,512)
        int row = idx >> 3, c = idx & 7;
        uint32_t sw = (uint32_t)(row * 128 + (((c ^ (row & 7)) & 7) << 4));
        cp16(ss + sw,          khi  + (size_t)(k0 + row) * HDD + c * 8);
        cp16(ss + 8192u + sw,  klo  + (size_t)(k0 + row) * HDD + c * 8);
        cp16(ss + 16384u + sw, vthi + (size_t)row * SS + k0 + c * 8);
        cp16(ss + 24576u + sw, vtlo + (size_t)row * SS + k0 + c * 8);
    }
}

__global__ __launch_bounds__(256, 1) void attn_mma_kernel()
{
    extern __shared__ char smem[];
    const uint32_t sb = smem_u32(smem);
    const int t = threadIdx.x, w = t >> 5, lane = t & 31;
    const int qt = blockIdx.x, h = blockIdx.y, b = blockIdx.z;
    const int q0 = qt * 128;
    const int bh = b * HH + h;
    const size_t qk_base = (size_t)bh * SS * HDD;
    const __nv_bfloat16* qhi  = g_qhi  + qk_base;
    const __nv_bfloat16* qlo  = g_qlo  + qk_base;
    const __nv_bfloat16* khi  = g_khi  + qk_base;
    const __nv_bfloat16* klo  = g_klo  + qk_base;
    const __nv_bfloat16* vthi = g_vthi + (size_t)bh * HDD * SS;
    const __nv_bfloat16* vtlo = g_vtlo + (size_t)bh * HDD * SS;

    // ---- stage Q (hi at sb, lo at sb+16K) and pull into A-fragments ----
#pragma unroll
    for (int i = 0; i < 4; ++i) {
        int idx = t + i * 256;           // [0,1024)
        int row = idx >> 3, c = idx & 7;
        uint32_t sw = (uint32_t)(row * 128 + (((c ^ (row & 7)) & 7) << 4));
        cp16(sb + sw,           qhi + (size_t)(q0 + row) * HDD + c * 8);
        cp16(sb + 16384u + sw,  qlo + (size_t)(q0 + row) * HDD + c * 8);
    }
    CP_COMMIT();
    CP_WAIT0();
    __syncthreads();

    uint32_t qh[4][4], ql[4][4];
    {
        int ar  = (lane & 7) + ((lane >> 3) & 1) * 8;
        int akc = lane >> 4;
        int r = w * 16 + ar;
#pragma unroll
        for (int ks = 0; ks < 4; ++ks) {
            int ch = ks * 2 + akc;
            uint32_t off = (uint32_t)(r * 128 + (((ch ^ (r & 7)) & 7) << 4));
            ldm_x4(qh[ks], sb + off);
            ldm_x4(ql[ks], sb + 16384u + off);
        }
    }
    __syncthreads();   // everyone done reading Q before stage0 is overwritten

    float o[8][4];
#pragma unroll
    for (int i = 0; i < 8; ++i)
#pragma unroll
        for (int e = 0; e < 4; ++e) o[i][e] = 0.0f;
    float m[2] = {-1e30f, -1e30f}, l[2] = {0.0f, 0.0f};

    const int nkt = 2 * qt + 2;

    attn_load(sb, khi, klo, vthi, vtlo, 0, t);
    CP_COMMIT();
    if (nkt > 1) attn_load(sb + A_STG, khi, klo, vthi, vtlo, 64, t);
    CP_COMMIT();

    const int b_r  = (lane & 7) + ((lane >> 4) & 1) * 8;
    const int b_kc = (lane >> 3) & 1;

    for (int kt = 0; kt < nkt; ++kt) {
        const int k0 = kt * 64;
        const uint32_t ss = sb + (uint32_t)(kt & 1) * A_STG;
        CP_WAIT1();
        __syncthreads();

        // ---- S = Q K^T, bf16x3 (qhi*Khi + qlo*Khi + qhi*Klo) ----
        float sc[8][4];
#pragma unroll
        for (int i = 0; i < 8; ++i)
#pragma unroll
            for (int e = 0; e < 4; ++e) sc[i][e] = 0.0f;

#pragma unroll
        for (int ks = 0; ks < 4; ++ks) {
            int ch = ks * 2 + b_kc;
#pragma unroll
            for (int g = 0; g < 4; ++g) {
                int r = g * 16 + b_r;
                uint32_t off = (uint32_t)(r * 128 + (((ch ^ (r & 7)) & 7) << 4));
                uint32_t bf[4];
                ldm_x4(bf, ss + off);               // Khi
                mma16816(sc[g*2],     qh[ks], bf);
                mma16816(sc[g*2 + 1], qh[ks], bf + 2);
                mma16816(sc[g*2],     ql[ks], bf);
                mma16816(sc[g*2 + 1], ql[ks], bf + 2);
                uint32_t bl[4];
                ldm_x4(bl, ss + 8192u + off);       // Klo
                mma16816(sc[g*2],     qh[ks], bl);
                mma16816(sc[g*2 + 1], qh[ks], bl + 2);
            }
        }

        // ---- causal mask (only diagonal-band tiles) ----
        if (kt >= 2 * qt) {
            int rb = q0 + w * 16 + (lane >> 2);
            int cb = k0 + 2 * (lane & 3);
#pragma unroll
            for (int nt = 0; nt < 8; ++nt) {
#pragma unroll
                for (int e = 0; e < 4; ++e) {
                    int r = rb + ((e >> 1) << 3);
                    int c = cb + nt * 8 + (e & 1);
                    if (c > r) sc[nt][e] = -1e30f;
                }
            }
        }

        // ---- online softmax (base-2; scale folded into Q) ----
#pragma unroll
        for (int grp = 0; grp < 2; ++grp) {
            float mx = -1e30f;
#pragma unroll
            for (int nt = 0; nt < 8; ++nt)
                mx = fmaxf(mx, fmaxf(sc[nt][grp*2], sc[nt][grp*2 + 1]));
            mx = fmaxf(mx, __shfl_xor_sync(0xffffffffu, mx, 1));
            mx = fmaxf(mx, __shfl_xor_sync(0xffffffffu, mx, 2));
            float mn = fmaxf(m[grp], mx);
            float corr = exp2p(m[grp] - mn);
            m[grp] = mn;
            float sum = 0.0f;
#pragma unroll
            for (int nt = 0; nt < 8; ++nt) {
                float p0 = exp2p(sc[nt][grp*2]     - mn);
                float p1 = exp2p(sc[nt][grp*2 + 1] - mn);
                sc[nt][grp*2] = p0; sc[nt][grp*2 + 1] = p1;
                sum += p0 + p1;
            }
            sum += __shfl_xor_sync(0xffffffffu, sum, 1);
            sum += __shfl_xor_sync(0xffffffffu, sum, 2);
            l[grp] = l[grp] * corr + sum;
#pragma unroll
            for (int nt = 0; nt < 8; ++nt) {
                o[nt][grp*2] *= corr; o[nt][grp*2 + 1] *= corr;
            }
        }

        // ---- P -> A fragments (hi/lo, in-register) ----
        uint32_t pha[4][4], pla[4][4];
#pragma unroll
        for (int kt4 = 0; kt4 < 4; ++kt4) {
#pragma unroll
            for (int j = 0; j < 4; ++j) {
                int nt = kt4 * 2 + (j >> 1);
                float p0 = sc[nt][(j & 1) * 2];
                float p1 = sc[nt][(j & 1) * 2 + 1];
                __nv_bfloat16 h0 = __float2bfloat16(p0);
                __nv_bfloat16 h1 = __float2bfloat16(p1);
                __nv_bfloat162 H; H.x = h0; H.y = h1;
                __nv_bfloat162 L;
                L.x = __float2bfloat16(p0 - __bfloat162float(h0));
                L.y = __float2bfloat16(p1 - __bfloat162float(h1));
                pha[kt4][j] = *reinterpret_cast<uint32_t*>(&H);
                pla[kt4][j] = *reinterpret_cast<uint32_t*>(&L);
            }
        }

        // ---- O += P V, bf16x3 (Phi*Vhi + Plo*Vhi + Phi*Vlo) ----
#pragma unroll
        for (int ks = 0; ks < 4; ++ks) {            // key 16-chunks
            int ch = ks * 2 + b_kc;
#pragma unroll
            for (int g = 0; g < 4; ++g) {           // hd 16-row groups
                int r = g * 16 + b_r;
                uint32_t off = (uint32_t)(r * 128 + (((ch ^ (r & 7)) & 7) << 4));
                uint32_t bf[4];
                ldm_x4(bf, ss + 16384u + off);      // Vthi
                mma16816(o[g*2],     pha[ks], bf);
                mma16816(o[g*2 + 1], pha[ks], bf + 2);
                mma16816(o[g*2],     pla[ks], bf);
                mma16816(o[g*2 + 1], pla[ks], bf + 2);
                uint32_t bl[4];
                ldm_x4(bl, ss + 24576u + off);      // Vtlo
                mma16816(o[g*2],     pha[ks], bl);
                mma16816(o[g*2 + 1], pha[ks], bl + 2);
            }
        }

        __syncthreads();
        if (kt + 2 < nkt)
            attn_load(ss, khi, klo, vthi, vtlo, (kt + 2) * 64, t);
        CP_COMMIT();
    }
    CP_WAIT0();

    // ---- epilogue: normalize, write fp32 g_o [b, s, h*64+hd] ----
#pragma unroll
    for (int grp = 0; grp < 2; ++grp) {
        float inv = 1.0f / l[grp];
        int row = q0 + w * 16 + (lane >> 2) + grp * 8;
        size_t base = ((size_t)b * SS + row) * DD + h * HDD + 2 * (lane & 3);
#pragma unroll
        for (int nt = 0; nt < 8; ++nt) {
            float2 v;
            v.x = o[nt][grp*2]     * inv;
            v.y = o[nt][grp*2 + 1] * inv;
            *(float2*)&g_o[base + nt * 8] = v;
        }
    }
}

// ---------------------------------------------------------------------------
// Output projection (fp32, bit-identical to round 1 — known good).
// ---------------------------------------------------------------------------
__global__ __launch_bounds__(256, 1) void proj_kernel(
    const float* __restrict__ Wp, const float* __restrict__ bp,
    float* __restrict__ out)
{
    const int mt = blockIdx.x;
    const int nt = blockIdx.y;
    const int m0 = mt * 128, n0 = nt * 64;

    __shared__ float As[16][132];
    __shared__ float Bs[16][64];

    const int t  = threadIdx.x;
    const int tx = t & 15, ty = t >> 4;
    const int lrow = t >> 2, lkg = t & 3;

    float acc[8][4];
#pragma unroll
    for (int i = 0; i < 8; ++i)
#pragma unroll
        for (int j = 0; j < 4; ++j) acc[i][j] = 0.0f;

    for (int k0 = 0; k0 < DD; k0 += 16) {
        float4 a0 = *(const float4*)&g_o[(size_t)(m0 + lrow)      * DD + k0 + lkg * 4];
        float4 a1 = *(const float4*)&g_o[(size_t)(m0 + lrow + 64) * DD + k0 + lkg * 4];
        float4 b0 = *(const float4*)&Wp[(size_t)(k0 + ty) * DD + n0 + tx * 4];
        __syncthreads();
        As[lkg*4 + 0][lrow] = a0.x; As[lkg*4 + 1][lrow] = a0.y;
        As[lkg*4 + 2][lrow] = a0.z; As[lkg*4 + 3][lrow] = a0.w;
        As[lkg*4 + 0][lrow + 64] = a1.x; As[lkg*4 + 1][lrow + 64] = a1.y;
        As[lkg*4 + 2][lrow + 64] = a1.z; As[lkg*4 + 3][lrow + 64] = a1.w;
        *(float4*)&Bs[ty][tx * 4] = b0;
        __syncthreads();
#pragma unroll
        for (int kk = 0; kk < 16; ++kk) {
            float4 a04 = *(const float4*)&As[kk][ty * 8];
            float4 a14 = *(const float4*)&As[kk][ty * 8 + 4];
            float4 bv4 = *(const float4*)&Bs[kk][tx * 4];
            float av[8] = {a04.x, a04.y, a04.z, a04.w, a14.x, a14.y, a14.z, a14.w};
            float bv_[4] = {bv4.x, bv4.y, bv4.z, bv4.w};
#pragma unroll
            for (int i = 0; i < 8; ++i)
#pragma unroll
                for (int j = 0; j < 4; ++j)
                    acc[i][j] = fmaf(av[i], bv_[j], acc[i][j]);
        }
    }

    float bb[4];
#pragma unroll
    for (int j = 0; j < 4; ++j) bb[j] = bp[n0 + tx * 4 + j];
#pragma unroll
    for (int i = 0; i < 8; ++i) {
        int r = m0 + ty * 8 + i;
        float4 v;
        v.x = acc[i][0] + bb[0];
        v.y = acc[i][1] + bb[1];
        v.z = acc[i][2] + bb[2];
        v.w = acc[i][3] + bb[3];
        *(float4*)&out[(size_t)r * DD + n0 + tx * 4] = v;
    }
}

// ---------------------------------------------------------------------------
extern "C" void kernel_launch(void* const* d_in, const int* in_sizes, int n_in,
                              void* d_out, int out_size)
{
    const float* x  = (const float*)d_in[0];
    const float* Wq = (const float*)d_in[1];
    const float* bq = (const float*)d_in[2];
    const float* Wk = (const float*)d_in[3];
    const float* bk = (const float*)d_in[4];
    const float* Wv = (const float*)d_in[5];
    const float* bv = (const float*)d_in[6];
    const float* Wp = (const float*)d_in[7];
    const float* bp = (const float*)d_in[8];
    float* out = (float*)d_out;

    cudaFuncSetAttribute(qkv_mma_kernel,
                         cudaFuncAttributeMaxDynamicSharedMemorySize, G_SMEM);
    cudaFuncSetAttribute(attn_mma_kernel,
                         cudaFuncAttributeMaxDynamicSharedMemorySize, A_SMEM);

    cvt_x_kernel<<<NTOK * DD / 1024, 256>>>(x);
    cvt_wqkv_kernel<<<3 * DD * 128 / 256, 256>>>(Wq, Wk, Wv, bq, bk, bv);

    qkv_mma_kernel<<<dim3(64, 24), 256, G_SMEM>>>();

    attn_mma_kernel<<<dim3(16, 16, 4), 256, A_SMEM>>>();

    proj_kernel<<<dim3(64, 16, 1), 256>>>(Wp, bp, out);

    (void)in_sizes; (void)n_in; (void)out_size;
}

// round 8
// speedup vs baseline: 2.3759x; 1.1432x over previous
#include <cuda_runtime.h>
#include <cuda_bf16.h>
#include <cstdint>

#define BB 4
#define SS 2048
#define DD 1024
#define HH 16
#define HDD 64
#define NTOK (BB*SS)

// ---------------- scratch ----------------
__device__ __nv_bfloat16 g_qhi[BB*HH*SS*HDD];   // [bh][s][hd], pre-scaled by 0.125*log2e
__device__ __nv_bfloat16 g_qlo[BB*HH*SS*HDD];
__device__ __nv_bfloat16 g_khi[BB*HH*SS*HDD];   // [bh][s][hd]
__device__ __nv_bfloat16 g_klo[BB*HH*SS*HDD];
__device__ __nv_bfloat16 g_vthi[BB*HH*HDD*SS];  // [bh][hd][s]  (transposed V)
__device__ __nv_bfloat16 g_vtlo[BB*HH*HDD*SS];

__device__ __nv_bfloat16 g_ohi[NTOK*DD];        // attention output, bf16 split
__device__ __nv_bfloat16 g_olo[NTOK*DD];

__device__ __nv_bfloat16 g_xhi[NTOK*DD];
__device__ __nv_bfloat16 g_xlo[NTOK*DD];
__device__ __nv_bfloat16 g_wqkv_hi[3*DD*DD];    // [n=3072][k=1024]
__device__ __nv_bfloat16 g_wqkv_lo[3*DD*DD];
__device__ __nv_bfloat16 g_wpt_hi[DD*DD];       // [n=1024][k=1024] = Wp^T
__device__ __nv_bfloat16 g_wpt_lo[DD*DD];
__device__ float g_biascat[3*DD];

// ---------------- helpers ----------------
static __device__ __forceinline__ uint32_t smem_u32(const void* p) {
    uint32_t a;
    asm("{ .reg .u64 t; cvta.to.shared.u64 t, %1; cvt.u32.u64 %0, t; }"
        : "=r"(a) : "l"(p));
    return a;
}

static __device__ __forceinline__ void cp16(uint32_t dst, const void* src) {
    asm volatile("cp.async.cg.shared.global [%0], [%1], 16;" :: "r"(dst), "l"(src));
}
#define CP_COMMIT() asm volatile("cp.async.commit_group;" ::: "memory")
#define CP_WAIT1()  asm volatile("cp.async.wait_group 1;" ::: "memory")
#define CP_WAIT0()  asm volatile("cp.async.wait_group 0;" ::: "memory")

static __device__ __forceinline__ void ldm_x4(uint32_t* r, uint32_t addr) {
    asm volatile("ldmatrix.sync.aligned.m8n8.x4.shared.b16 {%0,%1,%2,%3}, [%4];"
                 : "=r"(r[0]), "=r"(r[1]), "=r"(r[2]), "=r"(r[3]) : "r"(addr));
}

static __device__ __forceinline__ void mma16816(float* d, const uint32_t* a,
                                                const uint32_t* b) {
    asm volatile(
        "mma.sync.aligned.m16n8k16.row.col.f32.bf16.bf16.f32 "
        "{%0,%1,%2,%3}, {%4,%5,%6,%7}, {%8,%9}, {%0,%1,%2,%3};"
        : "+f"(d[0]), "+f"(d[1]), "+f"(d[2]), "+f"(d[3])
        : "r"(a[0]), "r"(a[1]), "r"(a[2]), "r"(a[3]), "r"(b[0]), "r"(b[1]));
}

// 2^t via FMA-pipe polynomial (deg-5, rel err <= ~1e-4); t <= 0 expected.
static __device__ __forceinline__ float exp2p(float t) {
    t = fmaxf(t, -126.0f);
    float n = floorf(t);
    float f = t - n;
    float p = 1.33333642e-3f;
    p = fmaf(p, f, 9.61812910e-3f);
    p = fmaf(p, f, 5.55041087e-2f);
    p = fmaf(p, f, 2.40226507e-1f);
    p = fmaf(p, f, 6.93147181e-1f);
    p = fmaf(p, f, 1.0f);
    return p * __int_as_float(((int)n + 127) << 23);
}

// ---------------- conversion kernels ----------------
__global__ __launch_bounds__(256) void cvt_x_kernel(const float* __restrict__ x)
{
    int idx = blockIdx.x * 256 + threadIdx.x;     // 4 elems each
    float4 v = *(const float4*)(x + (size_t)idx * 4);
    __nv_bfloat16 h0 = __float2bfloat16(v.x), h1 = __float2bfloat16(v.y);
    __nv_bfloat16 h2 = __float2bfloat16(v.z), h3 = __float2bfloat16(v.w);
    __nv_bfloat16 l0 = __float2bfloat16(v.x - __bfloat162float(h0));
    __nv_bfloat16 l1 = __float2bfloat16(v.y - __bfloat162float(h1));
    __nv_bfloat16 l2 = __float2bfloat16(v.z - __bfloat162float(h2));
    __nv_bfloat16 l3 = __float2bfloat16(v.w - __bfloat162float(h3));
    __nv_bfloat162* hp = (__nv_bfloat162*)g_xhi;
    __nv_bfloat162* lp = (__nv_bfloat162*)g_xlo;
    hp[idx * 2]     = __nv_bfloat162(h0, h1);
    hp[idx * 2 + 1] = __nv_bfloat162(h2, h3);
    lp[idx * 2]     = __nv_bfloat162(l0, l1);
    lp[idx * 2 + 1] = __nv_bfloat162(l2, l3);
}

// Wcat[n][k] = W[which][h][k][e], n = which*1024 + h*64 + e. Also biascat.
__global__ __launch_bounds__(256) void cvt_wqkv_kernel(
    const float* __restrict__ Wq, const float* __restrict__ Wk,
    const float* __restrict__ Wv, const float* __restrict__ bq,
    const float* __restrict__ bk, const float* __restrict__ bv)
{
    int gid = blockIdx.x * 256 + threadIdx.x;     // 3072 * 128
    int n = gid >> 7;
    int k0 = (gid & 127) << 3;
    int which = n >> 10, h = (n >> 6) & 15, e = n & 63;
    const float* W = which == 0 ? Wq : (which == 1 ? Wk : Wv);
    const float* base = W + (size_t)h * DD * HDD + e;
#pragma unroll
    for (int i = 0; i < 8; ++i) {
        float x = base[(size_t)(k0 + i) * HDD];
        __nv_bfloat16 hi = __float2bfloat16(x);
        __nv_bfloat16 lo = __float2bfloat16(x - __bfloat162float(hi));
        g_wqkv_hi[(size_t)n * DD + k0 + i] = hi;
        g_wqkv_lo[(size_t)n * DD + k0 + i] = lo;
    }
    if (k0 == 0) {
        const float* bb = which == 0 ? bq : (which == 1 ? bk : bv);
        g_biascat[n] = bb[h * HDD + e];
    }
}

// Wpt[n][k] = Wp[k][n]
__global__ __launch_bounds__(256) void cvt_wp_kernel(const float* __restrict__ Wp)
{
    int gid = blockIdx.x * 256 + threadIdx.x;     // 1024 * 128
    int n = gid >> 7;
    int k0 = (gid & 127) << 3;
#pragma unroll
    for (int i = 0; i < 8; ++i) {
        float x = Wp[(size_t)(k0 + i) * DD + n];
        __nv_bfloat16 hi = __float2bfloat16(x);
        __nv_bfloat16 lo = __float2bfloat16(x - __bfloat162float(hi));
        g_wpt_hi[(size_t)n * DD + k0 + i] = hi;
        g_wpt_lo[(size_t)n * DD + k0 + i] = lo;
    }
}

// ---------------- mma.sync GEMM (mainloop proven rounds 6-7) ----------------
#define G_STG   32768u
#define G_SMEM  (2 * 32768)
#define G_NCH   48

static __device__ __forceinline__ void g_load(
    uint32_t sA, uint32_t sB,
    const __nv_bfloat16* __restrict__ Asrc, const __nv_bfloat16* __restrict__ Bsrc,
    int m0, int n0, int kk, int t)
{
#pragma unroll
    for (int i = 0; i < 4; ++i) {
        int idx = t + i * 256;
        int row = idx >> 3, c = idx & 7;
        cp16(sA + row * 128 + (((c ^ (row & 7)) & 7) << 4),
             Asrc + (size_t)(m0 + row) * DD + kk + c * 8);
    }
#pragma unroll
    for (int i = 0; i < 4; ++i) {
        int idx = t + i * 256;
        int row = idx >> 3, c = idx & 7;
        cp16(sB + row * 128 + (((c ^ (row & 7)) & 7) << 4),
             Bsrc + (size_t)(n0 + row) * DD + kk + c * 8);
    }
}

template<int MODE>   // 0: QKV (x @ Wqkv^T), 1: proj (O @ Wp)
__global__ __launch_bounds__(256, 1) void gemm_kernel(
    const float* __restrict__ biasp, float* __restrict__ outp)
{
    extern __shared__ char smem[];
    const uint32_t sb = smem_u32(smem);
    const int t = threadIdx.x, wid = t >> 5, lane = t & 31;
    const int warp_m = wid & 1, warp_n = wid >> 1;
    const int m0 = blockIdx.x * 128, n0 = blockIdx.y * 128;

    const __nv_bfloat16 *Ahi, *Alo, *Bhi, *Blo;
    if (MODE == 0) { Ahi = g_xhi; Alo = g_xlo; Bhi = g_wqkv_hi; Blo = g_wqkv_lo; }
    else           { Ahi = g_ohi; Alo = g_olo; Bhi = g_wpt_hi;  Blo = g_wpt_lo; }

    float acc[4][4][4];
#pragma unroll
    for (int i = 0; i < 4; ++i)
#pragma unroll
        for (int j = 0; j < 4; ++j)
#pragma unroll
            for (int e = 0; e < 4; ++e) acc[i][j][e] = 0.0f;

    const int a_row = (lane & 7) + ((lane >> 3) & 1) * 8;
    const int a_kch = lane >> 4;
    const int b_nof = (lane & 7) + ((lane >> 4) & 1) * 8;
    const int b_kch = (lane >> 3) & 1;

    // chunk c: phase p = c>>4 (0: hi*hi, 1: hi*lo, 2: lo*hi), kk = (c&15)*64
#define ASRC(c) (((c) >> 4) < 2 ? Ahi : Alo)
#define BSRC(c) ((((c) >> 4) == 1) ? Blo : Bhi)

    g_load(sb,         sb + 16384u,          ASRC(0), BSRC(0), m0, n0, 0,  t);
    CP_COMMIT();
    g_load(sb + G_STG, sb + G_STG + 16384u,  ASRC(1), BSRC(1), m0, n0, 64, t);
    CP_COMMIT();

    for (int c = 0; c < G_NCH; ++c) {
        const uint32_t sA = sb + (c & 1) * G_STG;
        const uint32_t sB = sA + 16384u;
        CP_WAIT1();
        __syncthreads();

#pragma unroll
        for (int ks = 0; ks < 4; ++ks) {
            uint32_t afr[4][4];
#pragma unroll
            for (int mt = 0; mt < 4; ++mt) {
                int r = warp_m * 64 + mt * 16 + a_row;
                int ch = ks * 2 + a_kch;
                ldm_x4(afr[mt], sA + r * 128 + (((ch ^ (r & 7)) & 7) << 4));
            }
            uint32_t bfr[2][4];
#pragma unroll
            for (int g = 0; g < 2; ++g) {
                int r = warp_n * 32 + g * 16 + b_nof;
                int ch = ks * 2 + b_kch;
                ldm_x4(bfr[g], sB + r * 128 + (((ch ^ (r & 7)) & 7) << 4));
            }
#pragma unroll
            for (int mt = 0; mt < 4; ++mt)
#pragma unroll
                for (int nt = 0; nt < 4; ++nt)
                    mma16816(acc[mt][nt], afr[mt], &bfr[nt >> 1][(nt & 1) * 2]);
        }

        __syncthreads();
        if (c + 2 < G_NCH) {
            int cn = c + 2;
            g_load(sA, sB, ASRC(cn), BSRC(cn), m0, n0, (cn & 15) * 64, t);
        }
        CP_COMMIT();
    }
    CP_WAIT0();

    // Epilogue.
#pragma unroll
    for (int mt = 0; mt < 4; ++mt) {
#pragma unroll
        for (int nt = 0; nt < 4; ++nt) {
            int r0 = m0 + warp_m * 64 + mt * 16 + (lane >> 2);
            int c0 = n0 + warp_n * 32 + nt * 8 + (lane & 3) * 2;
            if (MODE == 0) {
                int which = c0 >> 10, hh2 = (c0 >> 6) & 15, e = c0 & 63;
                float scl = (which == 0) ? 0.18033688f : 1.0f;   // 0.125*log2(e)
#pragma unroll
                for (int half = 0; half < 2; ++half) {
                    int r = r0 + half * 8;
                    float y0 = (acc[mt][nt][half*2+0] + g_biascat[c0])     * scl;
                    float y1 = (acc[mt][nt][half*2+1] + g_biascat[c0 + 1]) * scl;
                    __nv_bfloat16 h0 = __float2bfloat16(y0), h1 = __float2bfloat16(y1);
                    __nv_bfloat16 lo0 = __float2bfloat16(y0 - __bfloat162float(h0));
                    __nv_bfloat16 lo1 = __float2bfloat16(y1 - __bfloat162float(h1));
                    int bb2 = r >> 11, s_ = r & (SS - 1);
                    int bh = bb2 * HH + hh2;
                    if (which == 2) {
                        size_t off = ((size_t)bh * HDD + e) * SS + s_;
                        g_vthi[off]      = h0;  g_vthi[off + SS] = h1;
                        g_vtlo[off]      = lo0; g_vtlo[off + SS] = lo1;
                    } else {
                        size_t off = ((size_t)bh * SS + s_) * HDD + e;
                        __nv_bfloat162 H; H.x = h0;  H.y = h1;
                        __nv_bfloat162 L; L.x = lo0; L.y = lo1;
                        __nv_bfloat16* dh = which == 0 ? g_qhi : g_khi;
                        __nv_bfloat16* dl = which == 0 ? g_qlo : g_klo;
                        *reinterpret_cast<__nv_bfloat162*>(dh + off) = H;
                        *reinterpret_cast<__nv_bfloat162*>(dl + off) = L;
                    }
                }
            } else {
#pragma unroll
                for (int half = 0; half < 2; ++half) {
                    int r = r0 + half * 8;
                    float2 w;
                    w.x = acc[mt][nt][half*2+0] + biasp[c0];
                    w.y = acc[mt][nt][half*2+1] + biasp[c0 + 1];
                    *(float2*)&outp[(size_t)r * DD + c0] = w;
                }
            }
        }
    }
}

// ---------------- mma.sync flash attention (proven round 7) ----------------
#define A_STG  32768u
#define A_SMEM (2 * 32768)

static __device__ __forceinline__ void attn_load(
    uint32_t ss, const __nv_bfloat16* __restrict__ khi,
    const __nv_bfloat16* __restrict__ klo,
    const __nv_bfloat16* __restrict__ vthi,
    const __nv_bfloat16* __restrict__ vtlo, int k0, int t)
{
#pragma unroll
    for (int i = 0; i < 2; ++i) {
        int idx = t + i * 256;           // [0,512)
        int row = idx >> 3, c = idx & 7;
        uint32_t sw = (uint32_t)(row * 128 + (((c ^ (row & 7)) & 7) << 4));
        cp16(ss + sw,          khi  + (size_t)(k0 + row) * HDD + c * 8);
        cp16(ss + 8192u + sw,  klo  + (size_t)(k0 + row) * HDD + c * 8);
        cp16(ss + 16384u + sw, vthi + (size_t)row * SS + k0 + c * 8);
        cp16(ss + 24576u + sw, vtlo + (size_t)row * SS + k0 + c * 8);
    }
}

__global__ __launch_bounds__(256, 1) void attn_mma_kernel()
{
    extern __shared__ char smem[];
    const uint32_t sb = smem_u32(smem);
    const int t = threadIdx.x, w = t >> 5, lane = t & 31;
    const int qt = blockIdx.x, h = blockIdx.y, b = blockIdx.z;
    const int q0 = qt * 128;
    const int bh = b * HH + h;
    const size_t qk_base = (size_t)bh * SS * HDD;
    const __nv_bfloat16* qhi  = g_qhi  + qk_base;
    const __nv_bfloat16* qlo  = g_qlo  + qk_base;
    const __nv_bfloat16* khi  = g_khi  + qk_base;
    const __nv_bfloat16* klo  = g_klo  + qk_base;
    const __nv_bfloat16* vthi = g_vthi + (size_t)bh * HDD * SS;
    const __nv_bfloat16* vtlo = g_vtlo + (size_t)bh * HDD * SS;

    // ---- stage Q (hi at sb, lo at sb+16K) and pull into A-fragments ----
#pragma unroll
    for (int i = 0; i < 4; ++i) {
        int idx = t + i * 256;           // [0,1024)
        int row = idx >> 3, c = idx & 7;
        uint32_t sw = (uint32_t)(row * 128 + (((c ^ (row & 7)) & 7) << 4));
        cp16(sb + sw,           qhi + (size_t)(q0 + row) * HDD + c * 8);
        cp16(sb + 16384u + sw,  qlo + (size_t)(q0 + row) * HDD + c * 8);
    }
    CP_COMMIT();
    CP_WAIT0();
    __syncthreads();

    uint32_t qh[4][4], ql[4][4];
    {
        int ar  = (lane & 7) + ((lane >> 3) & 1) * 8;
        int akc = lane >> 4;
        int r = w * 16 + ar;
#pragma unroll
        for (int ks = 0; ks < 4; ++ks) {
            int ch = ks * 2 + akc;
            uint32_t off = (uint32_t)(r * 128 + (((ch ^ (r & 7)) & 7) << 4));
            ldm_x4(qh[ks], sb + off);
            ldm_x4(ql[ks], sb + 16384u + off);
        }
    }
    __syncthreads();

    float o[8][4];
#pragma unroll
    for (int i = 0; i < 8; ++i)
#pragma unroll
        for (int e = 0; e < 4; ++e) o[i][e] = 0.0f;
    float m[2] = {-1e30f, -1e30f}, l[2] = {0.0f, 0.0f};

    const int nkt = 2 * qt + 2;

    attn_load(sb, khi, klo, vthi, vtlo, 0, t);
    CP_COMMIT();
    if (nkt > 1) attn_load(sb + A_STG, khi, klo, vthi, vtlo, 64, t);
    CP_COMMIT();

    const int b_r  = (lane & 7) + ((lane >> 4) & 1) * 8;
    const int b_kc = (lane >> 3) & 1;

    for (int kt = 0; kt < nkt; ++kt) {
        const int k0 = kt * 64;
        const uint32_t ss = sb + (uint32_t)(kt & 1) * A_STG;
        CP_WAIT1();
        __syncthreads();

        // ---- S = Q K^T, bf16x3 ----
        float sc[8][4];
#pragma unroll
        for (int i = 0; i < 8; ++i)
#pragma unroll
            for (int e = 0; e < 4; ++e) sc[i][e] = 0.0f;

#pragma unroll
        for (int ks = 0; ks < 4; ++ks) {
            int ch = ks * 2 + b_kc;
#pragma unroll
            for (int g = 0; g < 4; ++g) {
                int r = g * 16 + b_r;
                uint32_t off = (uint32_t)(r * 128 + (((ch ^ (r & 7)) & 7) << 4));
                uint32_t bf[4];
                ldm_x4(bf, ss + off);               // Khi
                mma16816(sc[g*2],     qh[ks], bf);
                mma16816(sc[g*2 + 1], qh[ks], bf + 2);
                mma16816(sc[g*2],     ql[ks], bf);
                mma16816(sc[g*2 + 1], ql[ks], bf + 2);
                uint32_t bl[4];
                ldm_x4(bl, ss + 8192u + off);       // Klo
                mma16816(sc[g*2],     qh[ks], bl);
                mma16816(sc[g*2 + 1], qh[ks], bl + 2);
            }
        }

        // ---- causal mask ----
        if (kt >= 2 * qt) {
            int rb = q0 + w * 16 + (lane >> 2);
            int cb = k0 + 2 * (lane & 3);
#pragma unroll
            for (int nt = 0; nt < 8; ++nt) {
#pragma unroll
                for (int e = 0; e < 4; ++e) {
                    int r = rb + ((e >> 1) << 3);
                    int c = cb + nt * 8 + (e & 1);
                    if (c > r) sc[nt][e] = -1e30f;
                }
            }
        }

        // ---- online softmax (base-2) ----
#pragma unroll
        for (int grp = 0; grp < 2; ++grp) {
            float mx = -1e30f;
#pragma unroll
            for (int nt = 0; nt < 8; ++nt)
                mx = fmaxf(mx, fmaxf(sc[nt][grp*2], sc[nt][grp*2 + 1]));
            mx = fmaxf(mx, __shfl_xor_sync(0xffffffffu, mx, 1));
            mx = fmaxf(mx, __shfl_xor_sync(0xffffffffu, mx, 2));
            float mn = fmaxf(m[grp], mx);
            float corr = exp2p(m[grp] - mn);
            m[grp] = mn;
            float sum = 0.0f;
#pragma unroll
            for (int nt = 0; nt < 8; ++nt) {
                float p0 = exp2p(sc[nt][grp*2]     - mn);
                float p1 = exp2p(sc[nt][grp*2 + 1] - mn);
                sc[nt][grp*2] = p0; sc[nt][grp*2 + 1] = p1;
                sum += p0 + p1;
            }
            sum += __shfl_xor_sync(0xffffffffu, sum, 1);
            sum += __shfl_xor_sync(0xffffffffu, sum, 2);
            l[grp] = l[grp] * corr + sum;
#pragma unroll
            for (int nt = 0; nt < 8; ++nt) {
                o[nt][grp*2] *= corr; o[nt][grp*2 + 1] *= corr;
            }
        }

        // ---- P -> A fragments (hi/lo) ----
        uint32_t pha[4][4], pla[4][4];
#pragma unroll
        for (int kt4 = 0; kt4 < 4; ++kt4) {
#pragma unroll
            for (int j = 0; j < 4; ++j) {
                int nt = kt4 * 2 + (j >> 1);
                float p0 = sc[nt][(j & 1) * 2];
                float p1 = sc[nt][(j & 1) * 2 + 1];
                __nv_bfloat16 h0 = __float2bfloat16(p0);
                __nv_bfloat16 h1 = __float2bfloat16(p1);
                __nv_bfloat162 H; H.x = h0; H.y = h1;
                __nv_bfloat162 L;
                L.x = __float2bfloat16(p0 - __bfloat162float(h0));
                L.y = __float2bfloat16(p1 - __bfloat162float(h1));
                pha[kt4][j] = *reinterpret_cast<uint32_t*>(&H);
                pla[kt4][j] = *reinterpret_cast<uint32_t*>(&L);
            }
        }

        // ---- O += P V, bf16x3 ----
#pragma unroll
        for (int ks = 0; ks < 4; ++ks) {
            int ch = ks * 2 + b_kc;
#pragma unroll
            for (int g = 0; g < 4; ++g) {
                int r = g * 16 + b_r;
                uint32_t off = (uint32_t)(r * 128 + (((ch ^ (r & 7)) & 7) << 4));
                uint32_t bf[4];
                ldm_x4(bf, ss + 16384u + off);      // Vthi
                mma16816(o[g*2],     pha[ks], bf);
                mma16816(o[g*2 + 1], pha[ks], bf + 2);
                mma16816(o[g*2],     pla[ks], bf);
                mma16816(o[g*2 + 1], pla[ks], bf + 2);
                uint32_t bl[4];
                ldm_x4(bl, ss + 24576u + off);      // Vtlo
                mma16816(o[g*2],     pha[ks], bl);
                mma16816(o[g*2 + 1], pha[ks], bl + 2);
            }
        }

        __syncthreads();
        if (kt + 2 < nkt)
            attn_load(ss, khi, klo, vthi, vtlo, (kt + 2) * 64, t);
        CP_COMMIT();
    }
    CP_WAIT0();

    // ---- epilogue: normalize, write bf16 hi/lo O [b*S+s][h*64+hd] ----
#pragma unroll
    for (int grp = 0; grp < 2; ++grp) {
        float inv = 1.0f / l[grp];
        int row = q0 + w * 16 + (lane >> 2) + grp * 8;
        size_t base = ((size_t)b * SS + row) * DD + h * HDD + 2 * (lane & 3);
#pragma unroll
        for (int nt = 0; nt < 8; ++nt) {
            float y0 = o[nt][grp*2]     * inv;
            float y1 = o[nt][grp*2 + 1] * inv;
            __nv_bfloat16 h0 = __float2bfloat16(y0);
            __nv_bfloat16 h1 = __float2bfloat16(y1);
            __nv_bfloat162 H; H.x = h0; H.y = h1;
            __nv_bfloat162 L;
            L.x = __float2bfloat16(y0 - __bfloat162float(h0));
            L.y = __float2bfloat16(y1 - __bfloat162float(h1));
            *reinterpret_cast<__nv_bfloat162*>(g_ohi + base + nt * 8) = H;
            *reinterpret_cast<__nv_bfloat162*>(g_olo + base + nt * 8) = L;
        }
    }
}

// ---------------------------------------------------------------------------
extern "C" void kernel_launch(void* const* d_in, const int* in_sizes, int n_in,
                              void* d_out, int out_size)
{
    const float* x  = (const float*)d_in[0];
    const float* Wq = (const float*)d_in[1];
    const float* bq = (const float*)d_in[2];
    const float* Wk = (const float*)d_in[3];
    const float* bk = (const float*)d_in[4];
    const float* Wv = (const float*)d_in[5];
    const float* bv = (const float*)d_in[6];
    const float* Wp = (const float*)d_in[7];
    const float* bp = (const float*)d_in[8];
    float* out = (float*)d_out;

    cudaFuncSetAttribute(gemm_kernel<0>,
                         cudaFuncAttributeMaxDynamicSharedMemorySize, G_SMEM);
    cudaFuncSetAttribute(gemm_kernel<1>,
                         cudaFuncAttributeMaxDynamicSharedMemorySize, G_SMEM);
    cudaFuncSetAttribute(attn_mma_kernel,
                         cudaFuncAttributeMaxDynamicSharedMemorySize, A_SMEM);

    cvt_x_kernel<<<NTOK * DD / 1024, 256>>>(x);
    cvt_wqkv_kernel<<<3 * DD * 128 / 256, 256>>>(Wq, Wk, Wv, bq, bk, bv);
    cvt_wp_kernel<<<DD * 128 / 256, 256>>>(Wp);

    gemm_kernel<0><<<dim3(64, 24), 256, G_SMEM>>>(nullptr, nullptr);

    attn_mma_kernel<<<dim3(16, 16, 4), 256, A_SMEM>>>();

    gemm_kernel<1><<<dim3(64, 8), 256, G_SMEM>>>(bp, out);

    (void)in_sizes; (void)n_in; (void)out_size;
}

// round 10
// speedup vs baseline: 2.4487x; 1.0306x over previous
#include <cuda_runtime.h>
#include <cuda_bf16.h>
#include <cstdint>

#define BB 4
#define SS 2048
#define DD 1024
#define HH 16
#define HDD 64
#define NTOK (BB*SS)

// ---------------- scratch ----------------
__device__ __nv_bfloat16 g_qhi[BB*HH*SS*HDD];   // [bh][s][hd], pre-scaled by 0.125*log2e
__device__ __nv_bfloat16 g_qlo[BB*HH*SS*HDD];
__device__ __nv_bfloat16 g_khi[BB*HH*SS*HDD];   // [bh][s][hd]
__device__ __nv_bfloat16 g_klo[BB*HH*SS*HDD];
__device__ __nv_bfloat16 g_vthi[BB*HH*HDD*SS];  // [bh][hd][s]  (transposed V)
__device__ __nv_bfloat16 g_vtlo[BB*HH*HDD*SS];

__device__ __nv_bfloat16 g_ohi[NTOK*DD];        // attention output, bf16 split
__device__ __nv_bfloat16 g_olo[NTOK*DD];

__device__ __nv_bfloat16 g_xhi[NTOK*DD];
__device__ __nv_bfloat16 g_xlo[NTOK*DD];
__device__ __nv_bfloat16 g_wqkv_hi[3*DD*DD];    // [n=3072][k=1024]
__device__ __nv_bfloat16 g_wqkv_lo[3*DD*DD];
__device__ __nv_bfloat16 g_wpt_hi[DD*DD];       // [n=1024][k=1024] = Wp^T
__device__ __nv_bfloat16 g_wpt_lo[DD*DD];
__device__ float g_biascat[3*DD];

// ---------------- helpers ----------------
static __device__ __forceinline__ uint32_t smem_u32(const void* p) {
    uint32_t a;
    asm("{ .reg .u64 t; cvta.to.shared.u64 t, %1; cvt.u32.u64 %0, t; }"
        : "=r"(a) : "l"(p));
    return a;
}

static __device__ __forceinline__ void cp16(uint32_t dst, const void* src) {
    asm volatile("cp.async.cg.shared.global [%0], [%1], 16;" :: "r"(dst), "l"(src));
}
#define CP_COMMIT() asm volatile("cp.async.commit_group;" ::: "memory")
#define CP_WAIT1()  asm volatile("cp.async.wait_group 1;" ::: "memory")
#define CP_WAIT0()  asm volatile("cp.async.wait_group 0;" ::: "memory")

static __device__ __forceinline__ void ldm_x4(uint32_t* r, uint32_t addr) {
    asm volatile("ldmatrix.sync.aligned.m8n8.x4.shared.b16 {%0,%1,%2,%3}, [%4];"
                 : "=r"(r[0]), "=r"(r[1]), "=r"(r[2]), "=r"(r[3]) : "r"(addr));
}

static __device__ __forceinline__ void mma16816(float* d, const uint32_t* a,
                                                const uint32_t* b) {
    asm volatile(
        "mma.sync.aligned.m16n8k16.row.col.f32.bf16.bf16.f32 "
        "{%0,%1,%2,%3}, {%4,%5,%6,%7}, {%8,%9}, {%0,%1,%2,%3};"
        : "+f"(d[0]), "+f"(d[1]), "+f"(d[2]), "+f"(d[3])
        : "r"(a[0]), "r"(a[1]), "r"(a[2]), "r"(a[3]), "r"(b[0]), "r"(b[1]));
}

// 2^t via FMA-pipe polynomial (deg-5, rel err <= ~1e-4); t <= 0 expected.
static __device__ __forceinline__ float exp2p(float t) {
    t = fmaxf(t, -126.0f);
    float n = floorf(t);
    float f = t - n;
    float p = 1.33333642e-3f;
    p = fmaf(p, f, 9.61812910e-3f);
    p = fmaf(p, f, 5.55041087e-2f);
    p = fmaf(p, f, 2.40226507e-1f);
    p = fmaf(p, f, 6.93147181e-1f);
    p = fmaf(p, f, 1.0f);
    return p * __int_as_float(((int)n + 127) << 23);
}

// ---------------- conversion kernels ----------------
__global__ __launch_bounds__(256) void cvt_x_kernel(const float* __restrict__ x)
{
    int idx = blockIdx.x * 256 + threadIdx.x;     // 4 elems each
    float4 v = *(const float4*)(x + (size_t)idx * 4);
    __nv_bfloat16 h0 = __float2bfloat16(v.x), h1 = __float2bfloat16(v.y);
    __nv_bfloat16 h2 = __float2bfloat16(v.z), h3 = __float2bfloat16(v.w);
    __nv_bfloat16 l0 = __float2bfloat16(v.x - __bfloat162float(h0));
    __nv_bfloat16 l1 = __float2bfloat16(v.y - __bfloat162float(h1));
    __nv_bfloat16 l2 = __float2bfloat16(v.z - __bfloat162float(h2));
    __nv_bfloat16 l3 = __float2bfloat16(v.w - __bfloat162float(h3));
    __nv_bfloat162* hp = (__nv_bfloat162*)g_xhi;
    __nv_bfloat162* lp = (__nv_bfloat162*)g_xlo;
    hp[idx * 2]     = __nv_bfloat162(h0, h1);
    hp[idx * 2 + 1] = __nv_bfloat162(h2, h3);
    lp[idx * 2]     = __nv_bfloat162(l0, l1);
    lp[idx * 2 + 1] = __nv_bfloat162(l2, l3);
}

// Wcat[n][k] = W[which][h][k][e], n = which*1024 + h*64 + e. Also biascat.
__global__ __launch_bounds__(256) void cvt_wqkv_kernel(
    const float* __restrict__ Wq, const float* __restrict__ Wk,
    const float* __restrict__ Wv, const float* __restrict__ bq,
    const float* __restrict__ bk, const float* __restrict__ bv)
{
    int gid = blockIdx.x * 256 + threadIdx.x;     // 3072 * 128
    int n = gid >> 7;
    int k0 = (gid & 127) << 3;
    int which = n >> 10, h = (n >> 6) & 15, e = n & 63;
    const float* W = which == 0 ? Wq : (which == 1 ? Wk : Wv);
    const float* base = W + (size_t)h * DD * HDD + e;
#pragma unroll
    for (int i = 0; i < 8; ++i) {
        float x = base[(size_t)(k0 + i) * HDD];
        __nv_bfloat16 hi = __float2bfloat16(x);
        __nv_bfloat16 lo = __float2bfloat16(x - __bfloat162float(hi));
        g_wqkv_hi[(size_t)n * DD + k0 + i] = hi;
        g_wqkv_lo[(size_t)n * DD + k0 + i] = lo;
    }
    if (k0 == 0) {
        const float* bb = which == 0 ? bq : (which == 1 ? bk : bv);
        g_biascat[n] = bb[h * HDD + e];
    }
}

// Wpt[n][k] = Wp[k][n]
__global__ __launch_bounds__(256) void cvt_wp_kernel(const float* __restrict__ Wp)
{
    int gid = blockIdx.x * 256 + threadIdx.x;     // 1024 * 128
    int n = gid >> 7;
    int k0 = (gid & 127) << 3;
#pragma unroll
    for (int i = 0; i < 8; ++i) {
        float x = Wp[(size_t)(k0 + i) * DD + n];
        __nv_bfloat16 hi = __float2bfloat16(x);
        __nv_bfloat16 lo = __float2bfloat16(x - __bfloat162float(hi));
        g_wpt_hi[(size_t)n * DD + k0 + i] = hi;
        g_wpt_lo[(size_t)n * DD + k0 + i] = lo;
    }
}

// ---------------- mma.sync GEMM ----------------
// BM=128, BN=64, BK=64, 256 thr (8 warps, 2x4), warp tile 64x16.
// Small tile => ~100 regs => 2 CTAs/SM with no spill.
// SMEM stage: A 16KB + B 8KB = 24KB, double buffered (48KB total).
#define G_STG   24576u
#define G_SMEM  (2 * 24576)
#define G_NCH   48

static __device__ __forceinline__ void g_load(
    uint32_t sA, uint32_t sB,
    const __nv_bfloat16* __restrict__ Asrc, const __nv_bfloat16* __restrict__ Bsrc,
    int m0, int n0, int kk, int t)
{
#pragma unroll
    for (int i = 0; i < 4; ++i) {
        int idx = t + i * 256;          // [0,1024): 128 rows x 8 chunks
        int row = idx >> 3, c = idx & 7;
        cp16(sA + row * 128 + (((c ^ (row & 7)) & 7) << 4),
             Asrc + (size_t)(m0 + row) * DD + kk + c * 8);
    }
#pragma unroll
    for (int i = 0; i < 2; ++i) {
        int idx = t + i * 256;          // [0,512): 64 rows x 8 chunks
        int row = idx >> 3, c = idx & 7;
        cp16(sB + row * 128 + (((c ^ (row & 7)) & 7) << 4),
             Bsrc + (size_t)(n0 + row) * DD + kk + c * 8);
    }
}

template<int MODE>   // 0: QKV (x @ Wqkv^T), 1: proj (O @ Wp)
__global__ __launch_bounds__(256, 2) void gemm_kernel(
    const float* __restrict__ biasp, float* __restrict__ outp)
{
    extern __shared__ char smem[];
    const uint32_t sb = smem_u32(smem);
    const int t = threadIdx.x, wid = t >> 5, lane = t & 31;
    const int warp_m = wid & 1, warp_n = wid >> 1;   // 2 x 4 warps
    const int m0 = blockIdx.x * 128, n0 = blockIdx.y * 64;

    const __nv_bfloat16 *Ahi, *Alo, *Bhi, *Blo;
    if (MODE == 0) { Ahi = g_xhi; Alo = g_xlo; Bhi = g_wqkv_hi; Blo = g_wqkv_lo; }
    else           { Ahi = g_ohi; Alo = g_olo; Bhi = g_wpt_hi;  Blo = g_wpt_lo; }

    float acc[4][2][4];
#pragma unroll
    for (int i = 0; i < 4; ++i)
#pragma unroll
        for (int j = 0; j < 2; ++j)
#pragma unroll
            for (int e = 0; e < 4; ++e) acc[i][j][e] = 0.0f;

    const int a_row = (lane & 7) + ((lane >> 3) & 1) * 8;
    const int a_kch = lane >> 4;
    const int b_nof = (lane & 7) + ((lane >> 4) & 1) * 8;
    const int b_kch = (lane >> 3) & 1;

    // chunk c: phase p = c>>4 (0: hi*hi, 1: hi*lo, 2: lo*hi), kk = (c&15)*64
#define ASRC(c) (((c) >> 4) < 2 ? Ahi : Alo)
#define BSRC(c) ((((c) >> 4) == 1) ? Blo : Bhi)

    g_load(sb,         sb + 16384u,          ASRC(0), BSRC(0), m0, n0, 0,  t);
    CP_COMMIT();
    g_load(sb + G_STG, sb + G_STG + 16384u,  ASRC(1), BSRC(1), m0, n0, 64, t);
    CP_COMMIT();

    for (int c = 0; c < G_NCH; ++c) {
        const uint32_t sA = sb + (c & 1) * G_STG;
        const uint32_t sB = sA + 16384u;
        CP_WAIT1();
        __syncthreads();

#pragma unroll
        for (int ks = 0; ks < 4; ++ks) {
            uint32_t afr[4][4];
#pragma unroll
            for (int mt = 0; mt < 4; ++mt) {
                int r = warp_m * 64 + mt * 16 + a_row;
                int ch = ks * 2 + a_kch;
                ldm_x4(afr[mt], sA + r * 128 + (((ch ^ (r & 7)) & 7) << 4));
            }
            uint32_t bfr[4];
            {
                int r = warp_n * 16 + b_nof;
                int ch = ks * 2 + b_kch;
                ldm_x4(bfr, sB + r * 128 + (((ch ^ (r & 7)) & 7) << 4));
            }
#pragma unroll
            for (int mt = 0; mt < 4; ++mt)
#pragma unroll
                for (int nt = 0; nt < 2; ++nt)
                    mma16816(acc[mt][nt], afr[mt], &bfr[nt * 2]);
        }

        __syncthreads();
        if (c + 2 < G_NCH) {
            int cn = c + 2;
            g_load(sA, sB, ASRC(cn), BSRC(cn), m0, n0, (cn & 15) * 64, t);
        }
        CP_COMMIT();
    }
    CP_WAIT0();

    // Epilogue.
#pragma unroll
    for (int mt = 0; mt < 4; ++mt) {
#pragma unroll
        for (int nt = 0; nt < 2; ++nt) {
            int r0 = m0 + warp_m * 64 + mt * 16 + (lane >> 2);
            int c0 = n0 + warp_n * 16 + nt * 8 + (lane & 3) * 2;
            if (MODE == 0) {
                int which = c0 >> 10, hh2 = (c0 >> 6) & 15, e = c0 & 63;
                float scl = (which == 0) ? 0.18033688f : 1.0f;   // 0.125*log2(e)
#pragma unroll
                for (int half = 0; half < 2; ++half) {
                    int r = r0 + half * 8;
                    float y0 = (acc[mt][nt][half*2+0] + g_biascat[c0])     * scl;
                    float y1 = (acc[mt][nt][half*2+1] + g_biascat[c0 + 1]) * scl;
                    __nv_bfloat16 h0 = __float2bfloat16(y0), h1 = __float2bfloat16(y1);
                    __nv_bfloat16 lo0 = __float2bfloat16(y0 - __bfloat162float(h0));
                    __nv_bfloat16 lo1 = __float2bfloat16(y1 - __bfloat162float(h1));
                    int bb2 = r >> 11, s_ = r & (SS - 1);
                    int bh = bb2 * HH + hh2;
                    if (which == 2) {
                        size_t off = ((size_t)bh * HDD + e) * SS + s_;
                        g_vthi[off]      = h0;  g_vthi[off + SS] = h1;
                        g_vtlo[off]      = lo0; g_vtlo[off + SS] = lo1;
                    } else {
                        size_t off = ((size_t)bh * SS + s_) * HDD + e;
                        __nv_bfloat162 H; H.x = h0;  H.y = h1;
                        __nv_bfloat162 L; L.x = lo0; L.y = lo1;
                        __nv_bfloat16* dh = which == 0 ? g_qhi : g_khi;
                        __nv_bfloat16* dl = which == 0 ? g_qlo : g_klo;
                        *reinterpret_cast<__nv_bfloat162*>(dh + off) = H;
                        *reinterpret_cast<__nv_bfloat162*>(dl + off) = L;
                    }
                }
            } else {
#pragma unroll
                for (int half = 0; half < 2; ++half) {
                    int r = r0 + half * 8;
                    float2 w;
                    w.x = acc[mt][nt][half*2+0] + biasp[c0];
                    w.y = acc[mt][nt][half*2+1] + biasp[c0 + 1];
                    *(float2*)&outp[(size_t)r * DD + c0] = w;
                }
            }
        }
    }
}

// ---------------- mma.sync flash attention (bit-identical to round 8) ----------------
#define A_STG  32768u
#define A_SMEM (2 * 32768)

static __device__ __forceinline__ void attn_load(
    uint32_t ss, const __nv_bfloat16* __restrict__ khi,
    const __nv_bfloat16* __restrict__ klo,
    const __nv_bfloat16* __restrict__ vthi,
    const __nv_bfloat16* __restrict__ vtlo, int k0, int t)
{
#pragma unroll
    for (int i = 0; i < 2; ++i) {
        int idx = t + i * 256;           // [0,512)
        int row = idx >> 3, c = idx & 7;
        uint32_t sw = (uint32_t)(row * 128 + (((c ^ (row & 7)) & 7) << 4));
        cp16(ss + sw,          khi  + (size_t)(k0 + row) * HDD + c * 8);
        cp16(ss + 8192u + sw,  klo  + (size_t)(k0 + row) * HDD + c * 8);
        cp16(ss + 16384u + sw, vthi + (size_t)row * SS + k0 + c * 8);
        cp16(ss + 24576u + sw, vtlo + (size_t)row * SS + k0 + c * 8);
    }
}

__global__ __launch_bounds__(256, 1) void attn_mma_kernel()
{
    extern __shared__ char smem[];
    const uint32_t sb = smem_u32(smem);
    const int t = threadIdx.x, w = t >> 5, lane = t & 31;
    const int qt = blockIdx.x, h = blockIdx.y, b = blockIdx.z;
    const int q0 = qt * 128;
    const int bh = b * HH + h;
    const size_t qk_base = (size_t)bh * SS * HDD;
    const __nv_bfloat16* qhi  = g_qhi  + qk_base;
    const __nv_bfloat16* qlo  = g_qlo  + qk_base;
    const __nv_bfloat16* khi  = g_khi  + qk_base;
    const __nv_bfloat16* klo  = g_klo  + qk_base;
    const __nv_bfloat16* vthi = g_vthi + (size_t)bh * HDD * SS;
    const __nv_bfloat16* vtlo = g_vtlo + (size_t)bh * HDD * SS;

    // ---- stage Q (hi at sb, lo at sb+16K) and pull into A-fragments ----
#pragma unroll
    for (int i = 0; i < 4; ++i) {
        int idx = t + i * 256;           // [0,1024)
        int row = idx >> 3, c = idx & 7;
        uint32_t sw = (uint32_t)(row * 128 + (((c ^ (row & 7)) & 7) << 4));
        cp16(sb + sw,           qhi + (size_t)(q0 + row) * HDD + c * 8);
        cp16(sb + 16384u + sw,  qlo + (size_t)(q0 + row) * HDD + c * 8);
    }
    CP_COMMIT();
    CP_WAIT0();
    __syncthreads();

    uint32_t qh[4][4], ql[4][4];
    {
        int ar  = (lane & 7) + ((lane >> 3) & 1) * 8;
        int akc = lane >> 4;
        int r = w * 16 + ar;
#pragma unroll
        for (int ks = 0; ks < 4; ++ks) {
            int ch = ks * 2 + akc;
            uint32_t off = (uint32_t)(r * 128 + (((ch ^ (r & 7)) & 7) << 4));
            ldm_x4(qh[ks], sb + off);
            ldm_x4(ql[ks], sb + 16384u + off);
        }
    }
    __syncthreads();

    float o[8][4];
#pragma unroll
    for (int i = 0; i < 8; ++i)
#pragma unroll
        for (int e = 0; e < 4; ++e) o[i][e] = 0.0f;
    float m[2] = {-1e30f, -1e30f}, l[2] = {0.0f, 0.0f};

    const int nkt = 2 * qt + 2;

    attn_load(sb, khi, klo, vthi, vtlo, 0, t);
    CP_COMMIT();
    if (nkt > 1) attn_load(sb + A_STG, khi, klo, vthi, vtlo, 64, t);
    CP_COMMIT();

    const int b_r  = (lane & 7) + ((lane >> 4) & 1) * 8;
    const int b_kc = (lane >> 3) & 1;

    for (int kt = 0; kt < nkt; ++kt) {
        const int k0 = kt * 64;
        const uint32_t ss = sb + (uint32_t)(kt & 1) * A_STG;
        CP_WAIT1();
        __syncthreads();

        // ---- S = Q K^T, bf16x3 ----
        float sc[8][4];
#pragma unroll
        for (int i = 0; i < 8; ++i)
#pragma unroll
            for (int e = 0; e < 4; ++e) sc[i][e] = 0.0f;

#pragma unroll
        for (int ks = 0; ks < 4; ++ks) {
            int ch = ks * 2 + b_kc;
#pragma unroll
            for (int g = 0; g < 4; ++g) {
                int r = g * 16 + b_r;
                uint32_t off = (uint32_t)(r * 128 + (((ch ^ (r & 7)) & 7) << 4));
                uint32_t bf[4];
                ldm_x4(bf, ss + off);               // Khi
                mma16816(sc[g*2],     qh[ks], bf);
                mma16816(sc[g*2 + 1], qh[ks], bf + 2);
                mma16816(sc[g*2],     ql[ks], bf);
                mma16816(sc[g*2 + 1], ql[ks], bf + 2);
                uint32_t bl[4];
                ldm_x4(bl, ss + 8192u + off);       // Klo
                mma16816(sc[g*2],     qh[ks], bl);
                mma16816(sc[g*2 + 1], qh[ks], bl + 2);
            }
        }

        // ---- causal mask ----
        if (kt >= 2 * qt) {
            int rb = q0 + w * 16 + (lane >> 2);
            int cb = k0 + 2 * (lane & 3);
#pragma unroll
            for (int nt = 0; nt < 8; ++nt) {
#pragma unroll
                for (int e = 0; e < 4; ++e) {
                    int r = rb + ((e >> 1) << 3);
                    int c = cb + nt * 8 + (e & 1);
                    if (c > r) sc[nt][e] = -1e30f;
                }
            }
        }

        // ---- online softmax (base-2) ----
#pragma unroll
        for (int grp = 0; grp < 2; ++grp) {
            float mx = -1e30f;
#pragma unroll
            for (int nt = 0; nt < 8; ++nt)
                mx = fmaxf(mx, fmaxf(sc[nt][grp*2], sc[nt][grp*2 + 1]));
            mx = fmaxf(mx, __shfl_xor_sync(0xffffffffu, mx, 1));
            mx = fmaxf(mx, __shfl_xor_sync(0xffffffffu, mx, 2));
            float mn = fmaxf(m[grp], mx);
            float corr = exp2p(m[grp] - mn);
            m[grp] = mn;
            float sum = 0.0f;
#pragma unroll
            for (int nt = 0; nt < 8; ++nt) {
                float p0 = exp2p(sc[nt][grp*2]     - mn);
                float p1 = exp2p(sc[nt][grp*2 + 1] - mn);
                sc[nt][grp*2] = p0; sc[nt][grp*2 + 1] = p1;
                sum += p0 + p1;
            }
            sum += __shfl_xor_sync(0xffffffffu, sum, 1);
            sum += __shfl_xor_sync(0xffffffffu, sum, 2);
            l[grp] = l[grp] * corr + sum;
#pragma unroll
            for (int nt = 0; nt < 8; ++nt) {
                o[nt][grp*2] *= corr; o[nt][grp*2 + 1] *= corr;
            }
        }

        // ---- P -> A fragments (hi/lo) ----
        uint32_t pha[4][4], pla[4][4];
#pragma unroll
        for (int kt4 = 0; kt4 < 4; ++kt4) {
#pragma unroll
            for (int j = 0; j < 4; ++j) {
                int nt = kt4 * 2 + (j >> 1);
                float p0 = sc[nt][(j & 1) * 2];
                float p1 = sc[nt][(j & 1) * 2 + 1];
                __nv_bfloat16 h0 = __float2bfloat16(p0);
                __nv_bfloat16 h1 = __float2bfloat16(p1);
                __nv_bfloat162 H; H.x = h0; H.y = h1;
                __nv_bfloat162 L;
                L.x = __float2bfloat16(p0 - __bfloat162float(h0));
                L.y = __float2bfloat16(p1 - __bfloat162float(h1));
                pha[kt4][j] = *reinterpret_cast<uint32_t*>(&H);
                pla[kt4][j] = *reinterpret_cast<uint32_t*>(&L);
            }
        }

        // ---- O += P V, bf16x3 ----
#pragma unroll
        for (int ks = 0; ks < 4; ++ks) {
            int ch = ks * 2 + b_kc;
#pragma unroll
            for (int g = 0; g < 4; ++g) {
                int r = g * 16 + b_r;
                uint32_t off = (uint32_t)(r * 128 + (((ch ^ (r & 7)) & 7) << 4));
                uint32_t bf[4];
                ldm_x4(bf, ss + 16384u + off);      // Vthi
                mma16816(o[g*2],     pha[ks], bf);
                mma16816(o[g*2 + 1], pha[ks], bf + 2);
                mma16816(o[g*2],     pla[ks], bf);
                mma16816(o[g*2 + 1], pla[ks], bf + 2);
                uint32_t bl[4];
                ldm_x4(bl, ss + 24576u + off);      // Vtlo
                mma16816(o[g*2],     pha[ks], bl);
                mma16816(o[g*2 + 1], pha[ks], bl + 2);
            }
        }

        __syncthreads();
        if (kt + 2 < nkt)
            attn_load(ss, khi, klo, vthi, vtlo, (kt + 2) * 64, t);
        CP_COMMIT();
    }
    CP_WAIT0();

    // ---- epilogue: normalize, write bf16 hi/lo O [b*S+s][h*64+hd] ----
#pragma unroll
    for (int grp = 0; grp < 2; ++grp) {
        float inv = 1.0f / l[grp];
        int row = q0 + w * 16 + (lane >> 2) + grp * 8;
        size_t base = ((size_t)b * SS + row) * DD + h * HDD + 2 * (lane & 3);
#pragma unroll
        for (int nt = 0; nt < 8; ++nt) {
            float y0 = o[nt][grp*2]     * inv;
            float y1 = o[nt][grp*2 + 1] * inv;
            __nv_bfloat16 h0 = __float2bfloat16(y0);
            __nv_bfloat16 h1 = __float2bfloat16(y1);
            __nv_bfloat162 H; H.x = h0; H.y = h1;
            __nv_bfloat162 L;
            L.x = __float2bfloat16(y0 - __bfloat162float(h0));
            L.y = __float2bfloat16(y1 - __bfloat162float(h1));
            *reinterpret_cast<__nv_bfloat162*>(g_ohi + base + nt * 8) = H;
            *reinterpret_cast<__nv_bfloat162*>(g_olo + base + nt * 8) = L;
        }
    }
}

// ---------------------------------------------------------------------------
extern "C" void kernel_launch(void* const* d_in, const int* in_sizes, int n_in,
                              void* d_out, int out_size)
{
    const float* x  = (const float*)d_in[0];
    const float* Wq = (const float*)d_in[1];
    const float* bq = (const float*)d_in[2];
    const float* Wk = (const float*)d_in[3];
    const float* bk = (const float*)d_in[4];
    const float* Wv = (const float*)d_in[5];
    const float* bv = (const float*)d_in[6];
    const float* Wp = (const float*)d_in[7];
    const float* bp = (const float*)d_in[8];
    float* out = (float*)d_out;

    cudaFuncSetAttribute(gemm_kernel<0>,
                         cudaFuncAttributeMaxDynamicSharedMemorySize, G_SMEM);
    cudaFuncSetAttribute(gemm_kernel<1>,
                         cudaFuncAttributeMaxDynamicSharedMemorySize, G_SMEM);
    cudaFuncSetAttribute(attn_mma_kernel,
                         cudaFuncAttributeMaxDynamicSharedMemorySize, A_SMEM);

    cvt_x_kernel<<<NTOK * DD / 1024, 256>>>(x);
    cvt_wqkv_kernel<<<3 * DD * 128 / 256, 256>>>(Wq, Wk, Wv, bq, bk, bv);
    cvt_wp_kernel<<<DD * 128 / 256, 256>>>(Wp);

    gemm_kernel<0><<<dim3(64, 48), 256, G_SMEM>>>(nullptr, nullptr);

    attn_mma_kernel<<<dim3(16, 16, 4), 256, A_SMEM>>>();

    gemm_kernel<1><<<dim3(64, 16), 256, G_SMEM>>>(bp, out);

    (void)in_sizes; (void)n_in; (void)out_size;
}